// round 1
// baseline (speedup 1.0000x reference)
#include <cuda_runtime.h>
#include <math.h>

#define NN   20000
#define EE   100000
#define DH   512
#define DOUT 256
#define HEADS 8
#define HID  64

// ---------------- scratch (device globals; no allocations allowed) ----------
__device__ float g_h  [NN * DH];
__device__ float g_h2 [NN * DH];
__device__ float g_xl [NN * DH];
__device__ float g_xr [NN * DH];
__device__ float g_acc[NN * DH];
__device__ float g_exps  [EE * HEADS];
__device__ float g_expsum[NN * HEADS];

// ---------------- SGEMM: C = act(A[MxK] * B[KxN] + bias) --------------------
#define BM 128
#define BN 128
#define BK 8
#define TM 8
#define TN 8

__global__ __launch_bounds__(256)
void sgemm_bias_act(const float* __restrict__ A, const float* __restrict__ B,
                    const float* __restrict__ bias, float* __restrict__ C,
                    int M, int N, int K, int act)
{
    __shared__ float As[BK][BM];
    __shared__ float Bs[BK][BN];

    int bx = blockIdx.x;           // N tile
    int by = blockIdx.y;           // M tile
    int tid = threadIdx.x;
    int tx = tid & 15;             // 16 thread cols
    int ty = tid >> 4;             // 16 thread rows

    int rowA = tid >> 1, colA = (tid & 1) * 4;     // A tile load: 128x8
    int rowB = tid >> 5, colB = (tid & 31) * 4;    // B tile load: 8x128

    float accr[TM][TN];
    #pragma unroll
    for (int i = 0; i < TM; i++)
        #pragma unroll
        for (int j = 0; j < TN; j++) accr[i][j] = 0.f;

    for (int k0 = 0; k0 < K; k0 += BK) {
        int gr = by * BM + rowA;
        float4 a4 = make_float4(0.f, 0.f, 0.f, 0.f);
        if (gr < M) a4 = *(const float4*)(A + (long)gr * K + k0 + colA);
        As[colA + 0][rowA] = a4.x;
        As[colA + 1][rowA] = a4.y;
        As[colA + 2][rowA] = a4.z;
        As[colA + 3][rowA] = a4.w;

        float4 b4 = *(const float4*)(B + (long)(k0 + rowB) * N + bx * BN + colB);
        *(float4*)&Bs[rowB][colB] = b4;
        __syncthreads();

        #pragma unroll
        for (int kk = 0; kk < BK; kk++) {
            float ra[TM], rb[TN];
            #pragma unroll
            for (int i = 0; i < TM; i++) ra[i] = As[kk][ty * TM + i];
            #pragma unroll
            for (int j = 0; j < TN; j++) rb[j] = Bs[kk][tx * TN + j];
            #pragma unroll
            for (int i = 0; i < TM; i++)
                #pragma unroll
                for (int j = 0; j < TN; j++)
                    accr[i][j] += ra[i] * rb[j];
        }
        __syncthreads();
    }

    #pragma unroll
    for (int i = 0; i < TM; i++) {
        int row = by * BM + ty * TM + i;
        if (row >= M) continue;
        #pragma unroll
        for (int j = 0; j < TN; j += 4) {
            int col = bx * BN + tx * TN + j;
            float4 v;
            v.x = accr[i][j + 0] + bias[col + 0];
            v.y = accr[i][j + 1] + bias[col + 1];
            v.z = accr[i][j + 2] + bias[col + 2];
            v.w = accr[i][j + 3] + bias[col + 3];
            if (act) {
                v.x = v.x > 0.f ? v.x : expm1f(v.x);
                v.y = v.y > 0.f ? v.y : expm1f(v.y);
                v.z = v.z > 0.f ? v.z : expm1f(v.z);
                v.w = v.w > 0.f ? v.w : expm1f(v.w);
            }
            *(float4*)(C + (long)row * N + col) = v;
        }
    }
}

// ---------------- helpers ---------------------------------------------------
__device__ __forceinline__ float warp_sum(float v) {
    #pragma unroll
    for (int o = 16; o; o >>= 1) v += __shfl_xor_sync(0xffffffffu, v, o);
    return v;
}

__device__ __forceinline__ void red_add_v4(float* p, float4 v) {
    asm volatile("red.global.add.v4.f32 [%0], {%1,%2,%3,%4};"
                 :: "l"(p), "f"(v.x), "f"(v.y), "f"(v.z), "f"(v.w) : "memory");
}

// ---------------- GATv2 edge kernels, layers 0/1 (heads=8, ch=64) ----------
// one block per edge, one warp per head. score -> exp -> atomic expsum.
__global__ __launch_bounds__(256)
void edge_scores_h8(const float* __restrict__ xl, const float* __restrict__ xr,
                    const int* __restrict__ src, const int* __restrict__ dst,
                    const float* __restrict__ att,  // [8,64]
                    float* __restrict__ exps, float* __restrict__ expsum)
{
    int e = blockIdx.x;
    int h = threadIdx.x >> 5;
    int lane = threadIdx.x & 31;
    int s = src[e], d = dst[e];
    const float* pl = xl + (long)s * DH + h * HID;
    const float* pr = xr + (long)d * DH + h * HID;
    const float* pa = att + h * HID;
    float acc = 0.f;
    #pragma unroll
    for (int c = lane; c < HID; c += 32) {
        float v = pl[c] + pr[c];
        v = v > 0.f ? v : 0.2f * v;
        acc += v * __ldg(pa + c);
    }
    acc = warp_sum(acc);
    if (lane == 0) {
        float w = expf(acc);
        exps[e * HEADS + h] = w;
        atomicAdd(&expsum[d * HEADS + h], w);
    }
}

// one block per edge, one warp per head; 16 lanes do a float4 red each.
__global__ __launch_bounds__(256)
void edge_agg_h8(const float* __restrict__ xl,
                 const int* __restrict__ src, const int* __restrict__ dst,
                 const float* __restrict__ exps, const float* __restrict__ expsum,
                 float* __restrict__ acc)
{
    int e = blockIdx.x;
    int h = threadIdx.x >> 5;
    int lane = threadIdx.x & 31;
    int s = src[e], d = dst[e];
    float alpha = exps[e * HEADS + h] / expsum[d * HEADS + h];
    if (lane < 16) {
        float4 v = *((const float4*)(xl + (long)s * DH + h * HID) + lane);
        v.x *= alpha; v.y *= alpha; v.z *= alpha; v.w *= alpha;
        red_add_v4(acc + (long)d * DH + h * HID + lane * 4, v);
    }
}

// ---------------- layer 2 edge kernels (heads=1, ch=256) --------------------
// one warp per edge; 8 edges per 256-thread block.
__global__ __launch_bounds__(256)
void edge_scores_c256(const float* __restrict__ xl, const float* __restrict__ xr,
                      const int* __restrict__ src, const int* __restrict__ dst,
                      const float* __restrict__ att,  // [256]
                      float* __restrict__ exps, float* __restrict__ expsum)
{
    int e = blockIdx.x * 8 + (threadIdx.x >> 5);
    if (e >= EE) return;
    int lane = threadIdx.x & 31;
    int s = src[e], d = dst[e];
    const float* pl = xl + (long)s * DOUT;
    const float* pr = xr + (long)d * DOUT;
    float acc = 0.f;
    #pragma unroll
    for (int c = lane; c < DOUT; c += 32) {
        float v = pl[c] + pr[c];
        v = v > 0.f ? v : 0.2f * v;
        acc += v * __ldg(att + c);
    }
    acc = warp_sum(acc);
    if (lane == 0) {
        float w = expf(acc);
        exps[e] = w;
        atomicAdd(&expsum[d], w);
    }
}

__global__ __launch_bounds__(256)
void edge_agg_c256(const float* __restrict__ xl,
                   const int* __restrict__ src, const int* __restrict__ dst,
                   const float* __restrict__ exps, const float* __restrict__ expsum,
                   float* __restrict__ acc)
{
    int e = blockIdx.x * 8 + (threadIdx.x >> 5);
    if (e >= EE) return;
    int lane = threadIdx.x & 31;
    int s = src[e], d = dst[e];
    float alpha = exps[e] / expsum[d];
    #pragma unroll
    for (int half = 0; half < 2; half++) {
        int c = half * 128 + lane * 4;
        float4 v = *(const float4*)(xl + (long)s * DOUT + c);
        v.x *= alpha; v.y *= alpha; v.z *= alpha; v.w *= alpha;
        red_add_v4(acc + (long)d * DOUT + c, v);
    }
}

// ---------------- fused elementwise: elu + residual + layernorm -------------
__global__ __launch_bounds__(128)
void fuse_elu_res_ln512(const float* __restrict__ acc, const float* __restrict__ res,
                        const float* __restrict__ b0, const float* __restrict__ b1,
                        const float* __restrict__ b2,
                        const float* __restrict__ gamma, const float* __restrict__ beta,
                        float* __restrict__ out)
{
    int i = blockIdx.x;
    int t = threadIdx.x;
    float v[4];
    float s = 0.f, s2 = 0.f;
    #pragma unroll
    for (int j = 0; j < 4; j++) {
        int c = j * 128 + t;
        float x = acc[(long)i * DH + c] + b0[c] + b1[c] + b2[c];
        x = x > 0.f ? x : expm1f(x);
        x += res[(long)i * DH + c];
        v[j] = x; s += x; s2 += x * x;
    }
    s = warp_sum(s); s2 = warp_sum(s2);
    __shared__ float sh1[4], sh2[4];
    int w = t >> 5, l = t & 31;
    if (l == 0) { sh1[w] = s; sh2[w] = s2; }
    __syncthreads();
    s = sh1[0] + sh1[1] + sh1[2] + sh1[3];
    s2 = sh2[0] + sh2[1] + sh2[2] + sh2[3];
    float mu = s * (1.f / DH);
    float var = s2 * (1.f / DH) - mu * mu;
    float inv = rsqrtf(var + 1e-5f);
    #pragma unroll
    for (int j = 0; j < 4; j++) {
        int c = j * 128 + t;
        out[(long)i * DH + c] = (v[j] - mu) * inv * gamma[c] + beta[c];
    }
}

__global__ __launch_bounds__(128)
void fuse_elu_ln256(const float* __restrict__ acc,
                    const float* __restrict__ b0, const float* __restrict__ b1,
                    const float* __restrict__ b2,
                    const float* __restrict__ gamma, const float* __restrict__ beta,
                    float* __restrict__ out)
{
    int i = blockIdx.x;
    int t = threadIdx.x;
    float v[2];
    float s = 0.f, s2 = 0.f;
    #pragma unroll
    for (int j = 0; j < 2; j++) {
        int c = j * 128 + t;
        float x = acc[(long)i * DOUT + c] + b0[c] + b1[c] + b2[c];
        x = x > 0.f ? x : expm1f(x);
        v[j] = x; s += x; s2 += x * x;
    }
    s = warp_sum(s); s2 = warp_sum(s2);
    __shared__ float sh1[4], sh2[4];
    int w = t >> 5, l = t & 31;
    if (l == 0) { sh1[w] = s; sh2[w] = s2; }
    __syncthreads();
    s = sh1[0] + sh1[1] + sh1[2] + sh1[3];
    s2 = sh2[0] + sh2[1] + sh2[2] + sh2[3];
    float mu = s * (1.f / DOUT);
    float var = s2 * (1.f / DOUT) - mu * mu;
    float inv = rsqrtf(var + 1e-5f);
    #pragma unroll
    for (int j = 0; j < 2; j++) {
        int c = j * 128 + t;
        out[(long)i * DOUT + c] = (v[j] - mu) * inv * gamma[c] + beta[c];
    }
}

// ---------------- host ------------------------------------------------------
static inline void run_gemm(const float* A, const float* B, const float* bias,
                            float* C, int M, int N, int K, int act)
{
    dim3 grid(N / BN, (M + BM - 1) / BM);
    sgemm_bias_act<<<grid, 256>>>(A, B, bias, C, M, N, K, act);
}

extern "C" void kernel_launch(void* const* d_in, const int* in_sizes, int n_in,
                              void* d_out, int out_size)
{
    const float* x          = (const float*)d_in[0];
    const int*   edge_index = (const int*)  d_in[1];
    const float* proj_w     = (const float*)d_in[2];
    const float* proj_b     = (const float*)d_in[3];
    const float* l01_ll_w   = (const float*)d_in[4];
    const float* l01_ll_b   = (const float*)d_in[5];
    const float* l01_lr_w   = (const float*)d_in[6];
    const float* l01_lr_b   = (const float*)d_in[7];
    const float* l01_att    = (const float*)d_in[8];
    const float* l01_bias   = (const float*)d_in[9];
    const float* l2_ll_w    = (const float*)d_in[10];
    const float* l2_ll_b    = (const float*)d_in[11];
    const float* l2_lr_w    = (const float*)d_in[12];
    const float* l2_lr_b    = (const float*)d_in[13];
    const float* l2_att     = (const float*)d_in[14];
    const float* l2_bias    = (const float*)d_in[15];
    const float* ln01_gamma = (const float*)d_in[16];
    const float* ln01_beta  = (const float*)d_in[17];
    const float* ln2_gamma  = (const float*)d_in[18];
    const float* ln2_beta   = (const float*)d_in[19];

    float *h, *h2, *xl, *xr, *acc, *exps, *expsum;
    cudaGetSymbolAddress((void**)&h,      g_h);
    cudaGetSymbolAddress((void**)&h2,     g_h2);
    cudaGetSymbolAddress((void**)&xl,     g_xl);
    cudaGetSymbolAddress((void**)&xr,     g_xr);
    cudaGetSymbolAddress((void**)&acc,    g_acc);
    cudaGetSymbolAddress((void**)&exps,   g_exps);
    cudaGetSymbolAddress((void**)&expsum, g_expsum);

    // input projection + ELU
    run_gemm(x, proj_w, proj_b, h, NN, DH, DH, 1);

    float* cur = h;
    float* nxt = h2;

    for (int li = 0; li < 2; li++) {
        cudaMemsetAsync(acc, 0, (size_t)NN * DH * sizeof(float));
        for (int et = 0; et < 3; et++) {
            const float* Wl = l01_ll_w + ((size_t)(li * 3 + et)) * DH * DH;
            const float* bl = l01_ll_b + (size_t)(li * 3 + et) * DH;
            const float* Wr = l01_lr_w + ((size_t)(li * 3 + et)) * DH * DH;
            const float* br = l01_lr_b + (size_t)(li * 3 + et) * DH;
            const float* at = l01_att  + (size_t)(li * 3 + et) * HEADS * HID;
            const int* src = edge_index + (size_t)et * 2 * EE;
            const int* dst = src + EE;

            run_gemm(cur, Wl, bl, xl, NN, DH, DH, 0);
            run_gemm(cur, Wr, br, xr, NN, DH, DH, 0);
            cudaMemsetAsync(expsum, 0, (size_t)NN * HEADS * sizeof(float));
            edge_scores_h8<<<EE, 256>>>(xl, xr, src, dst, at, exps, expsum);
            edge_agg_h8<<<EE, 256>>>(xl, src, dst, exps, expsum, acc);
        }
        fuse_elu_res_ln512<<<NN, 128>>>(acc, cur,
                                        l01_bias + (size_t)(li * 3 + 0) * DH,
                                        l01_bias + (size_t)(li * 3 + 1) * DH,
                                        l01_bias + (size_t)(li * 3 + 2) * DH,
                                        ln01_gamma + (size_t)li * DH,
                                        ln01_beta  + (size_t)li * DH,
                                        nxt);
        float* tmp = cur; cur = nxt; nxt = tmp;
    }

    // layer 2 (heads=1, out=256); reuse xl/xr/acc scratch
    cudaMemsetAsync(acc, 0, (size_t)NN * DOUT * sizeof(float));
    for (int et = 0; et < 3; et++) {
        const float* Wl = l2_ll_w + (size_t)et * DH * DOUT;
        const float* bl = l2_ll_b + (size_t)et * DOUT;
        const float* Wr = l2_lr_w + (size_t)et * DH * DOUT;
        const float* br = l2_lr_b + (size_t)et * DOUT;
        const float* at = l2_att  + (size_t)et * DOUT;
        const int* src = edge_index + (size_t)et * 2 * EE;
        const int* dst = src + EE;

        run_gemm(cur, Wl, bl, xl, NN, DOUT, DH, 0);
        run_gemm(cur, Wr, br, xr, NN, DOUT, DH, 0);
        cudaMemsetAsync(expsum, 0, (size_t)NN * sizeof(float));
        edge_scores_c256<<<(EE + 7) / 8, 256>>>(xl, xr, src, dst, at, exps, expsum);
        edge_agg_c256<<<(EE + 7) / 8, 256>>>(xl, src, dst, exps, expsum, acc);
    }
    fuse_elu_ln256<<<NN, 128>>>(acc,
                                l2_bias + 0 * DOUT, l2_bias + 1 * DOUT, l2_bias + 2 * DOUT,
                                ln2_gamma, ln2_beta, (float*)d_out);
}

// round 3
// speedup vs baseline: 2.5205x; 2.5205x over previous
#include <cuda_runtime.h>
#include <cuda_fp16.h>
#include <stdint.h>
#include <math.h>

#define NN   20000
#define EE   100000
#define DH   512
#define DOUT 256
#define HEADS 8
#define HID  64

// ---------------- scratch (device globals; no allocations allowed) ----------
__device__ float g_h  [NN * DH];
__device__ float g_h2 [NN * DH];
__device__ float g_xl [NN * DH];
__device__ float g_xr [NN * DH];
__device__ float g_acc[NN * DH];
__device__ float g_exps  [EE * HEADS];
__device__ float g_expsum[NN * HEADS];

// ---------------- fp16 tensor-core GEMM: C = act(A[MxK] * B[KxN] + bias) ----
// A row-major fp32, B row-major fp32; converted to fp16 during SMEM staging.
// Block tile 128x128, K tile 32, 8 warps (2x4), warp tile 64x32.
// mma.sync.m16n8k16 f16 inputs, f32 accumulate.

#define GBM 128
#define GBN 128
#define GBK 32
#define APAD 8     // A row = 32+8 = 40 halves = 80B -> conflict-free ldmatrix
#define BPAD 8     // B row = 128+8 = 136 halves = 272B -> conflict-free ldmatrix.trans

__device__ __forceinline__ uint32_t sptr(const void* p) {
    return (uint32_t)__cvta_generic_to_shared(p);
}

__global__ __launch_bounds__(256)
void hgemm_bias_act(const float* __restrict__ A, const float* __restrict__ B,
                    const float* __restrict__ bias, float* __restrict__ C,
                    int M, int N, int K, int act)
{
    __shared__ __align__(16) __half As[GBM][GBK + APAD];
    __shared__ __align__(16) __half Bs[GBK][GBN + BPAD];

    int tid  = threadIdx.x;
    int lane = tid & 31;
    int wid  = tid >> 5;
    int warp_m = wid >> 2;          // 0..1
    int warp_n = wid & 3;           // 0..3
    int m0 = warp_m * 64;
    int n0 = warp_n * 32;
    int bx = blockIdx.x, by = blockIdx.y;

    float acc[4][4][4];
    #pragma unroll
    for (int mi = 0; mi < 4; mi++)
        #pragma unroll
        for (int ni = 0; ni < 4; ni++)
            #pragma unroll
            for (int r = 0; r < 4; r++) acc[mi][ni][r] = 0.f;

    // precomputed ldmatrix SMEM addresses (bytes)
    // A: row = m0 + mi*16 + (lane&15), col = ks + (lane>>4)*8
    uint32_t a_base[4];
    #pragma unroll
    for (int mi = 0; mi < 4; mi++)
        a_base[mi] = sptr(&As[m0 + mi * 16 + (lane & 15)][(lane >> 4) * 8]);
    // B: row = ks + (lane&15), col = n0 + ni*8
    uint32_t b_base[4];
    #pragma unroll
    for (int ni = 0; ni < 4; ni++)
        b_base[ni] = sptr(&Bs[lane & 15][n0 + ni * 8]);

    for (int k0 = 0; k0 < K; k0 += GBK) {
        // ---- stage A tile (128x32 fp32 -> fp16) ----
        #pragma unroll
        for (int i = 0; i < 4; i++) {
            int l = tid + i * 256;           // 0..1023
            int row = l >> 3, c4 = l & 7;
            int gr = by * GBM + row;
            float4 v = make_float4(0.f, 0.f, 0.f, 0.f);
            if (gr < M) v = *(const float4*)(A + (long)gr * K + k0 + c4 * 4);
            union { __half2 h[2]; uint2 u; } p;
            p.h[0] = __floats2half2_rn(v.x, v.y);
            p.h[1] = __floats2half2_rn(v.z, v.w);
            *(uint2*)&As[row][c4 * 4] = p.u;
        }
        // ---- stage B tile (32x128 fp32 -> fp16) ----
        #pragma unroll
        for (int i = 0; i < 4; i++) {
            int l = tid + i * 256;
            int row = l >> 5, c4 = l & 31;
            float4 v = *(const float4*)(B + (long)(k0 + row) * N + bx * GBN + c4 * 4);
            union { __half2 h[2]; uint2 u; } p;
            p.h[0] = __floats2half2_rn(v.x, v.y);
            p.h[1] = __floats2half2_rn(v.z, v.w);
            *(uint2*)&Bs[row][c4 * 4] = p.u;
        }
        __syncthreads();

        #pragma unroll
        for (int ks = 0; ks < GBK; ks += 16) {
            uint32_t af[4][4], bf[4][2];
            #pragma unroll
            for (int mi = 0; mi < 4; mi++) {
                uint32_t addr = a_base[mi] + ks * 2;
                asm volatile("ldmatrix.sync.aligned.m8n8.x4.shared.b16 {%0,%1,%2,%3}, [%4];"
                             : "=r"(af[mi][0]), "=r"(af[mi][1]), "=r"(af[mi][2]), "=r"(af[mi][3])
                             : "r"(addr));
            }
            #pragma unroll
            for (int ni = 0; ni < 4; ni++) {
                uint32_t addr = b_base[ni] + ks * (GBN + BPAD) * 2;
                asm volatile("ldmatrix.sync.aligned.m8n8.x2.trans.shared.b16 {%0,%1}, [%2];"
                             : "=r"(bf[ni][0]), "=r"(bf[ni][1])
                             : "r"(addr));
            }
            #pragma unroll
            for (int mi = 0; mi < 4; mi++)
                #pragma unroll
                for (int ni = 0; ni < 4; ni++) {
                    asm volatile(
                        "mma.sync.aligned.m16n8k16.row.col.f32.f16.f16.f32 "
                        "{%0,%1,%2,%3},{%4,%5,%6,%7},{%8,%9},{%0,%1,%2,%3};"
                        : "+f"(acc[mi][ni][0]), "+f"(acc[mi][ni][1]),
                          "+f"(acc[mi][ni][2]), "+f"(acc[mi][ni][3])
                        : "r"(af[mi][0]), "r"(af[mi][1]), "r"(af[mi][2]), "r"(af[mi][3]),
                          "r"(bf[ni][0]), "r"(bf[ni][1]));
                }
        }
        __syncthreads();
    }

    // ---- epilogue: bias (+ optional ELU), fp32 out ----
    #pragma unroll
    for (int mi = 0; mi < 4; mi++) {
        int r0 = by * GBM + m0 + mi * 16 + (lane >> 2);
        #pragma unroll
        for (int ni = 0; ni < 4; ni++) {
            int c = bx * GBN + n0 + ni * 8 + (lane & 3) * 2;
            float bx0 = bias[c], bx1 = bias[c + 1];
            #pragma unroll
            for (int half_ = 0; half_ < 2; half_++) {
                int r = r0 + half_ * 8;
                if (r >= M) continue;
                float v0 = acc[mi][ni][half_ * 2 + 0] + bx0;
                float v1 = acc[mi][ni][half_ * 2 + 1] + bx1;
                if (act) {
                    v0 = v0 > 0.f ? v0 : expm1f(v0);
                    v1 = v1 > 0.f ? v1 : expm1f(v1);
                }
                float2 out = make_float2(v0, v1);
                *(float2*)(C + (long)r * N + c) = out;
            }
        }
    }
}

// ---------------- helpers ---------------------------------------------------
__device__ __forceinline__ float warp_sum(float v) {
    #pragma unroll
    for (int o = 16; o; o >>= 1) v += __shfl_xor_sync(0xffffffffu, v, o);
    return v;
}

__device__ __forceinline__ void red_add_v4(float* p, float4 v) {
    asm volatile("red.global.add.v4.f32 [%0], {%1,%2,%3,%4};"
                 :: "l"(p), "f"(v.x), "f"(v.y), "f"(v.z), "f"(v.w) : "memory");
}

// ---------------- GATv2 edge kernels, layers 0/1 (heads=8, ch=64) ----------
__global__ __launch_bounds__(256)
void edge_scores_h8(const float* __restrict__ xl, const float* __restrict__ xr,
                    const int* __restrict__ src, const int* __restrict__ dst,
                    const float* __restrict__ att,  // [8,64]
                    float* __restrict__ exps, float* __restrict__ expsum)
{
    int e = blockIdx.x;
    int h = threadIdx.x >> 5;
    int lane = threadIdx.x & 31;
    int s = src[e], d = dst[e];
    const float* pl = xl + (long)s * DH + h * HID;
    const float* pr = xr + (long)d * DH + h * HID;
    const float* pa = att + h * HID;
    float acc = 0.f;
    #pragma unroll
    for (int c = lane; c < HID; c += 32) {
        float v = pl[c] + pr[c];
        v = v > 0.f ? v : 0.2f * v;
        acc += v * __ldg(pa + c);
    }
    acc = warp_sum(acc);
    if (lane == 0) {
        float w = expf(acc);
        exps[e * HEADS + h] = w;
        atomicAdd(&expsum[d * HEADS + h], w);
    }
}

__global__ __launch_bounds__(256)
void edge_agg_h8(const float* __restrict__ xl,
                 const int* __restrict__ src, const int* __restrict__ dst,
                 const float* __restrict__ exps, const float* __restrict__ expsum,
                 float* __restrict__ acc)
{
    int e = blockIdx.x;
    int h = threadIdx.x >> 5;
    int lane = threadIdx.x & 31;
    int s = src[e], d = dst[e];
    float alpha = exps[e * HEADS + h] / expsum[d * HEADS + h];
    if (lane < 16) {
        float4 v = *((const float4*)(xl + (long)s * DH + h * HID) + lane);
        v.x *= alpha; v.y *= alpha; v.z *= alpha; v.w *= alpha;
        red_add_v4(acc + (long)d * DH + h * HID + lane * 4, v);
    }
}

// ---------------- layer 2 edge kernels (heads=1, ch=256) --------------------
__global__ __launch_bounds__(256)
void edge_scores_c256(const float* __restrict__ xl, const float* __restrict__ xr,
                      const int* __restrict__ src, const int* __restrict__ dst,
                      const float* __restrict__ att,  // [256]
                      float* __restrict__ exps, float* __restrict__ expsum)
{
    int e = blockIdx.x * 8 + (threadIdx.x >> 5);
    if (e >= EE) return;
    int lane = threadIdx.x & 31;
    int s = src[e], d = dst[e];
    const float* pl = xl + (long)s * DOUT;
    const float* pr = xr + (long)d * DOUT;
    float acc = 0.f;
    #pragma unroll
    for (int c = lane; c < DOUT; c += 32) {
        float v = pl[c] + pr[c];
        v = v > 0.f ? v : 0.2f * v;
        acc += v * __ldg(att + c);
    }
    acc = warp_sum(acc);
    if (lane == 0) {
        float w = expf(acc);
        exps[e] = w;
        atomicAdd(&expsum[d], w);
    }
}

__global__ __launch_bounds__(256)
void edge_agg_c256(const float* __restrict__ xl,
                   const int* __restrict__ src, const int* __restrict__ dst,
                   const float* __restrict__ exps, const float* __restrict__ expsum,
                   float* __restrict__ acc)
{
    int e = blockIdx.x * 8 + (threadIdx.x >> 5);
    if (e >= EE) return;
    int lane = threadIdx.x & 31;
    int s = src[e], d = dst[e];
    float alpha = exps[e] / expsum[d];
    #pragma unroll
    for (int half = 0; half < 2; half++) {
        int c = half * 128 + lane * 4;
        float4 v = *(const float4*)(xl + (long)s * DOUT + c);
        v.x *= alpha; v.y *= alpha; v.z *= alpha; v.w *= alpha;
        red_add_v4(acc + (long)d * DOUT + c, v);
    }
}

// ---------------- fused elementwise: elu + residual + layernorm -------------
__global__ __launch_bounds__(128)
void fuse_elu_res_ln512(const float* __restrict__ acc, const float* __restrict__ res,
                        const float* __restrict__ b0, const float* __restrict__ b1,
                        const float* __restrict__ b2,
                        const float* __restrict__ gamma, const float* __restrict__ beta,
                        float* __restrict__ out)
{
    int i = blockIdx.x;
    int t = threadIdx.x;
    float v[4];
    float s = 0.f, s2 = 0.f;
    #pragma unroll
    for (int j = 0; j < 4; j++) {
        int c = j * 128 + t;
        float x = acc[(long)i * DH + c] + b0[c] + b1[c] + b2[c];
        x = x > 0.f ? x : expm1f(x);
        x += res[(long)i * DH + c];
        v[j] = x; s += x; s2 += x * x;
    }
    s = warp_sum(s); s2 = warp_sum(s2);
    __shared__ float sh1[4], sh2[4];
    int w = t >> 5, l = t & 31;
    if (l == 0) { sh1[w] = s; sh2[w] = s2; }
    __syncthreads();
    s = sh1[0] + sh1[1] + sh1[2] + sh1[3];
    s2 = sh2[0] + sh2[1] + sh2[2] + sh2[3];
    float mu = s * (1.f / DH);
    float var = s2 * (1.f / DH) - mu * mu;
    float inv = rsqrtf(var + 1e-5f);
    #pragma unroll
    for (int j = 0; j < 4; j++) {
        int c = j * 128 + t;
        out[(long)i * DH + c] = (v[j] - mu) * inv * gamma[c] + beta[c];
    }
}

__global__ __launch_bounds__(128)
void fuse_elu_ln256(const float* __restrict__ acc,
                    const float* __restrict__ b0, const float* __restrict__ b1,
                    const float* __restrict__ b2,
                    const float* __restrict__ gamma, const float* __restrict__ beta,
                    float* __restrict__ out)
{
    int i = blockIdx.x;
    int t = threadIdx.x;
    float v[2];
    float s = 0.f, s2 = 0.f;
    #pragma unroll
    for (int j = 0; j < 2; j++) {
        int c = j * 128 + t;
        float x = acc[(long)i * DOUT + c] + b0[c] + b1[c] + b2[c];
        x = x > 0.f ? x : expm1f(x);
        v[j] = x; s += x; s2 += x * x;
    }
    s = warp_sum(s); s2 = warp_sum(s2);
    __shared__ float sh1[4], sh2[4];
    int w = t >> 5, l = t & 31;
    if (l == 0) { sh1[w] = s; sh2[w] = s2; }
    __syncthreads();
    s = sh1[0] + sh1[1] + sh1[2] + sh1[3];
    s2 = sh2[0] + sh2[1] + sh2[2] + sh2[3];
    float mu = s * (1.f / DOUT);
    float var = s2 * (1.f / DOUT) - mu * mu;
    float inv = rsqrtf(var + 1e-5f);
    #pragma unroll
    for (int j = 0; j < 2; j++) {
        int c = j * 128 + t;
        out[(long)i * DOUT + c] = (v[j] - mu) * inv * gamma[c] + beta[c];
    }
}

// ---------------- host ------------------------------------------------------
static inline void run_gemm(const float* A, const float* B, const float* bias,
                            float* C, int M, int N, int K, int act)
{
    dim3 grid(N / GBN, (M + GBM - 1) / GBM);
    hgemm_bias_act<<<grid, 256>>>(A, B, bias, C, M, N, K, act);
}

extern "C" void kernel_launch(void* const* d_in, const int* in_sizes, int n_in,
                              void* d_out, int out_size)
{
    const float* x          = (const float*)d_in[0];
    const int*   edge_index = (const int*)  d_in[1];
    const float* proj_w     = (const float*)d_in[2];
    const float* proj_b     = (const float*)d_in[3];
    const float* l01_ll_w   = (const float*)d_in[4];
    const float* l01_ll_b   = (const float*)d_in[5];
    const float* l01_lr_w   = (const float*)d_in[6];
    const float* l01_lr_b   = (const float*)d_in[7];
    const float* l01_att    = (const float*)d_in[8];
    const float* l01_bias   = (const float*)d_in[9];
    const float* l2_ll_w    = (const float*)d_in[10];
    const float* l2_ll_b    = (const float*)d_in[11];
    const float* l2_lr_w    = (const float*)d_in[12];
    const float* l2_lr_b    = (const float*)d_in[13];
    const float* l2_att     = (const float*)d_in[14];
    const float* l2_bias    = (const float*)d_in[15];
    const float* ln01_gamma = (const float*)d_in[16];
    const float* ln01_beta  = (const float*)d_in[17];
    const float* ln2_gamma  = (const float*)d_in[18];
    const float* ln2_beta   = (const float*)d_in[19];

    float *h, *h2, *xl, *xr, *acc, *exps, *expsum;
    cudaGetSymbolAddress((void**)&h,      g_h);
    cudaGetSymbolAddress((void**)&h2,     g_h2);
    cudaGetSymbolAddress((void**)&xl,     g_xl);
    cudaGetSymbolAddress((void**)&xr,     g_xr);
    cudaGetSymbolAddress((void**)&acc,    g_acc);
    cudaGetSymbolAddress((void**)&exps,   g_exps);
    cudaGetSymbolAddress((void**)&expsum, g_expsum);

    // input projection + ELU
    run_gemm(x, proj_w, proj_b, h, NN, DH, DH, 1);

    float* cur = h;
    float* nxt = h2;

    for (int li = 0; li < 2; li++) {
        cudaMemsetAsync(acc, 0, (size_t)NN * DH * sizeof(float));
        for (int et = 0; et < 3; et++) {
            const float* Wl = l01_ll_w + ((size_t)(li * 3 + et)) * DH * DH;
            const float* bl = l01_ll_b + (size_t)(li * 3 + et) * DH;
            const float* Wr = l01_lr_w + ((size_t)(li * 3 + et)) * DH * DH;
            const float* br = l01_lr_b + (size_t)(li * 3 + et) * DH;
            const float* at = l01_att  + (size_t)(li * 3 + et) * HEADS * HID;
            const int* src = edge_index + (size_t)et * 2 * EE;
            const int* dst = src + EE;

            run_gemm(cur, Wl, bl, xl, NN, DH, DH, 0);
            run_gemm(cur, Wr, br, xr, NN, DH, DH, 0);
            cudaMemsetAsync(expsum, 0, (size_t)NN * HEADS * sizeof(float));
            edge_scores_h8<<<EE, 256>>>(xl, xr, src, dst, at, exps, expsum);
            edge_agg_h8<<<EE, 256>>>(xl, src, dst, exps, expsum, acc);
        }
        fuse_elu_res_ln512<<<NN, 128>>>(acc, cur,
                                        l01_bias + (size_t)(li * 3 + 0) * DH,
                                        l01_bias + (size_t)(li * 3 + 1) * DH,
                                        l01_bias + (size_t)(li * 3 + 2) * DH,
                                        ln01_gamma + (size_t)li * DH,
                                        ln01_beta  + (size_t)li * DH,
                                        nxt);
        float* tmp = cur; cur = nxt; nxt = tmp;
    }

    // layer 2 (heads=1, out=256); reuse xl/xr/acc scratch
    cudaMemsetAsync(acc, 0, (size_t)NN * DOUT * sizeof(float));
    for (int et = 0; et < 3; et++) {
        const float* Wl = l2_ll_w + (size_t)et * DH * DOUT;
        const float* bl = l2_ll_b + (size_t)et * DOUT;
        const float* Wr = l2_lr_w + (size_t)et * DH * DOUT;
        const float* br = l2_lr_b + (size_t)et * DOUT;
        const float* at = l2_att  + (size_t)et * DOUT;
        const int* src = edge_index + (size_t)et * 2 * EE;
        const int* dst = src + EE;

        run_gemm(cur, Wl, bl, xl, NN, DOUT, DH, 0);
        run_gemm(cur, Wr, br, xr, NN, DOUT, DH, 0);
        cudaMemsetAsync(expsum, 0, (size_t)NN * sizeof(float));
        edge_scores_c256<<<(EE + 7) / 8, 256>>>(xl, xr, src, dst, at, exps, expsum);
        edge_agg_c256<<<(EE + 7) / 8, 256>>>(xl, src, dst, exps, expsum, acc);
    }
    fuse_elu_ln256<<<NN, 128>>>(acc,
                                l2_bias + 0 * DOUT, l2_bias + 1 * DOUT, l2_bias + 2 * DOUT,
                                ln2_gamma, ln2_beta, (float*)d_out);
}

// round 4
// speedup vs baseline: 4.8806x; 1.9363x over previous
#include <cuda_runtime.h>
#include <cuda_fp16.h>
#include <stdint.h>
#include <math.h>

#define NN   20000
#define EE   100000
#define DH   512
#define DOUT 256
#define HEADS 8
#define HID  64

// ---------------- scratch (device globals; no allocations allowed) ----------
__device__ float g_h  [NN * DH];
__device__ float g_h2 [NN * DH];
__device__ float g_xl [NN * DH];
__device__ float g_xr [NN * DH];
__device__ float g_acc[NN * DH];
__device__ float g_exps  [EE * HEADS];
__device__ float g_expsum[NN * HEADS];

__device__ __half g_a16 [NN * DH];                    // fp16 activation (GEMM A)
__device__ __half g_x16 [NN * DH];                    // fp16 input x
__device__ __half g_w16_proj [DH * DH];
__device__ __half g_w16_l01l [2 * 3 * DH * DH];
__device__ __half g_w16_l01r [2 * 3 * DH * DH];
__device__ __half g_w16_l2l  [3 * DH * DOUT];
__device__ __half g_w16_l2r  [3 * DH * DOUT];

// ---------------- fp32 -> fp16 converter ------------------------------------
__global__ __launch_bounds__(256)
void f32_to_f16(const float* __restrict__ in, __half* __restrict__ out, int n4)
{
    int i = blockIdx.x * 256 + threadIdx.x;
    if (i >= n4) return;
    float4 v = ((const float4*)in)[i];
    union { __half2 h[2]; uint2 u; } p;
    p.h[0] = __floats2half2_rn(v.x, v.y);
    p.h[1] = __floats2half2_rn(v.z, v.w);
    ((uint2*)out)[i] = p.u;
}

// ---------------- fp16 tensor-core GEMM (cp.async 2-stage pipeline) ---------
// A fp16 row-major [MxK], B fp16 row-major [KxN]. C = act(A*B + bias) fp32,
// optional fp16 copy C16. Block 128x128, K-tile 32, 8 warps (2x4), warp 64x32.

#define GBM 128
#define GBN 128
#define GBK 32
#define APAD 8     // A row = 40 halves = 80B (16B multiple, conflict-free)
#define BPAD 8     // B row = 136 halves = 272B (16B multiple, conflict-free)
#define A_STAGE_BYTES (GBM * (GBK + APAD) * 2)
#define B_STAGE_BYTES (GBK * (GBN + BPAD) * 2)

__device__ __forceinline__ uint32_t sptr(const void* p) {
    return (uint32_t)__cvta_generic_to_shared(p);
}
__device__ __forceinline__ void cp_async16(uint32_t dst, const void* src) {
    asm volatile("cp.async.cg.shared.global [%0], [%1], 16;" :: "r"(dst), "l"(src));
}
__device__ __forceinline__ void cp_commit() {
    asm volatile("cp.async.commit_group;");
}
template <int N> __device__ __forceinline__ void cp_wait() {
    asm volatile("cp.async.wait_group %0;" :: "n"(N));
}

__global__ __launch_bounds__(256)
void hgemm_bias_act(const __half* __restrict__ A, const __half* __restrict__ B,
                    const float* __restrict__ bias, float* __restrict__ C,
                    __half* __restrict__ C16, int M, int N, int K, int act)
{
    __shared__ __align__(16) __half As[2][GBM][GBK + APAD];
    __shared__ __align__(16) __half Bs[2][GBK][GBN + BPAD];

    int tid  = threadIdx.x;
    int lane = tid & 31;
    int wid  = tid >> 5;
    int m0 = (wid >> 2) * 64;
    int n0 = (wid & 3) * 32;
    int bx = blockIdx.x, by = blockIdx.y;

    // cp.async chunk mapping (16B = 8 halves per chunk)
    int a_row0 = tid >> 2,  a_off0 = (tid & 3) * 8;          // chunks 0..255
    int a_row1 = (tid + 256) >> 2, a_off1 = a_off0;          // chunks 256..511
    int b_row0 = tid >> 4,  b_off0 = (tid & 15) * 8;
    int b_row1 = (tid + 256) >> 4, b_off1 = b_off0;

    uint32_t As0 = sptr(&As[0][0][0]);
    uint32_t Bs0 = sptr(&Bs[0][0][0]);

    float acc[4][4][4];
    #pragma unroll
    for (int mi = 0; mi < 4; mi++)
        #pragma unroll
        for (int ni = 0; ni < 4; ni++)
            #pragma unroll
            for (int r = 0; r < 4; r++) acc[mi][ni][r] = 0.f;

    // ldmatrix base addresses (stage 0)
    uint32_t a_base[4];
    #pragma unroll
    for (int mi = 0; mi < 4; mi++)
        a_base[mi] = sptr(&As[0][m0 + mi * 16 + (lane & 15)][(lane >> 4) * 8]);
    uint32_t b_base[4];
    #pragma unroll
    for (int ni = 0; ni < 4; ni++)
        b_base[ni] = sptr(&Bs[0][lane & 15][n0 + ni * 8]);

    int gr0 = by * GBM + a_row0; if (gr0 >= M) gr0 = M - 1;
    int gr1 = by * GBM + a_row1; if (gr1 >= M) gr1 = M - 1;

    // prologue: load k0 = 0 into stage 0
    {
        cp_async16(As0 + a_row0 * 80 + a_off0 * 2, A + (long)gr0 * K + a_off0);
        cp_async16(As0 + a_row1 * 80 + a_off1 * 2, A + (long)gr1 * K + a_off1);
        cp_async16(Bs0 + b_row0 * 272 + b_off0 * 2, B + (long)b_row0 * N + bx * GBN + b_off0);
        cp_async16(Bs0 + b_row1 * 272 + b_off1 * 2, B + (long)b_row1 * N + bx * GBN + b_off1);
        cp_commit();
    }

    int iters = K / GBK;
    for (int it = 0; it < iters; it++) {
        if (it + 1 < iters) {
            int k0 = (it + 1) * GBK;
            int st = (it + 1) & 1;
            uint32_t Ad = As0 + st * A_STAGE_BYTES;
            uint32_t Bd = Bs0 + st * B_STAGE_BYTES;
            cp_async16(Ad + a_row0 * 80 + a_off0 * 2, A + (long)gr0 * K + k0 + a_off0);
            cp_async16(Ad + a_row1 * 80 + a_off1 * 2, A + (long)gr1 * K + k0 + a_off1);
            cp_async16(Bd + b_row0 * 272 + b_off0 * 2, B + (long)(k0 + b_row0) * N + bx * GBN + b_off0);
            cp_async16(Bd + b_row1 * 272 + b_off1 * 2, B + (long)(k0 + b_row1) * N + bx * GBN + b_off1);
            cp_commit();
            cp_wait<1>();
        } else {
            cp_wait<0>();
        }
        __syncthreads();

        int st = it & 1;
        uint32_t aofs = st * A_STAGE_BYTES;
        uint32_t bofs = st * B_STAGE_BYTES;
        #pragma unroll
        for (int ks = 0; ks < GBK; ks += 16) {
            uint32_t af[4][4], bf[4][2];
            #pragma unroll
            for (int mi = 0; mi < 4; mi++) {
                asm volatile("ldmatrix.sync.aligned.m8n8.x4.shared.b16 {%0,%1,%2,%3}, [%4];"
                             : "=r"(af[mi][0]), "=r"(af[mi][1]), "=r"(af[mi][2]), "=r"(af[mi][3])
                             : "r"(a_base[mi] + aofs + ks * 2));
            }
            #pragma unroll
            for (int ni = 0; ni < 4; ni++) {
                asm volatile("ldmatrix.sync.aligned.m8n8.x2.trans.shared.b16 {%0,%1}, [%2];"
                             : "=r"(bf[ni][0]), "=r"(bf[ni][1])
                             : "r"(b_base[ni] + bofs + ks * (GBN + BPAD) * 2));
            }
            #pragma unroll
            for (int mi = 0; mi < 4; mi++)
                #pragma unroll
                for (int ni = 0; ni < 4; ni++) {
                    asm volatile(
                        "mma.sync.aligned.m16n8k16.row.col.f32.f16.f16.f32 "
                        "{%0,%1,%2,%3},{%4,%5,%6,%7},{%8,%9},{%0,%1,%2,%3};"
                        : "+f"(acc[mi][ni][0]), "+f"(acc[mi][ni][1]),
                          "+f"(acc[mi][ni][2]), "+f"(acc[mi][ni][3])
                        : "r"(af[mi][0]), "r"(af[mi][1]), "r"(af[mi][2]), "r"(af[mi][3]),
                          "r"(bf[ni][0]), "r"(bf[ni][1]));
                }
        }
        __syncthreads();
    }

    // epilogue
    #pragma unroll
    for (int mi = 0; mi < 4; mi++) {
        int r0 = by * GBM + m0 + mi * 16 + (lane >> 2);
        #pragma unroll
        for (int ni = 0; ni < 4; ni++) {
            int c = bx * GBN + n0 + ni * 8 + (lane & 3) * 2;
            float bx0 = bias[c], bx1 = bias[c + 1];
            #pragma unroll
            for (int half_ = 0; half_ < 2; half_++) {
                int r = r0 + half_ * 8;
                if (r >= M) continue;
                float v0 = acc[mi][ni][half_ * 2 + 0] + bx0;
                float v1 = acc[mi][ni][half_ * 2 + 1] + bx1;
                if (act) {
                    v0 = v0 > 0.f ? v0 : expm1f(v0);
                    v1 = v1 > 0.f ? v1 : expm1f(v1);
                }
                *(float2*)(C + (long)r * N + c) = make_float2(v0, v1);
                if (C16)
                    *(__half2*)(C16 + (long)r * N + c) = __floats2half2_rn(v0, v1);
            }
        }
    }
}

// ---------------- helpers ---------------------------------------------------
__device__ __forceinline__ float warp_sum(float v) {
    #pragma unroll
    for (int o = 16; o; o >>= 1) v += __shfl_xor_sync(0xffffffffu, v, o);
    return v;
}

__device__ __forceinline__ void red_add_v4(float* p, float4 v) {
    asm volatile("red.global.add.v4.f32 [%0], {%1,%2,%3,%4};"
                 :: "l"(p), "f"(v.x), "f"(v.y), "f"(v.z), "f"(v.w) : "memory");
}

// ---------------- GATv2 edge kernels, layers 0/1 (heads=8, ch=64) ----------
// warp per edge; channel c = j*128 + lane*4, head = j*2 + (lane>>4)
__global__ __launch_bounds__(256)
void edge_scores_h8(const float* __restrict__ xl, const float* __restrict__ xr,
                    const int* __restrict__ src, const int* __restrict__ dst,
                    const float* __restrict__ att,  // [8,64]
                    float* __restrict__ exps, float* __restrict__ expsum)
{
    int e = blockIdx.x * 8 + (threadIdx.x >> 5);
    int lane = threadIdx.x & 31;
    int s = src[e], d = dst[e];
    const float4* pl = (const float4*)(xl + (long)s * DH);
    const float4* pr = (const float4*)(xr + (long)d * DH);
    float hsum[4];
    #pragma unroll
    for (int j = 0; j < 4; j++) {
        int idx = j * 32 + lane;
        float4 a = pl[idx];
        float4 b = pr[idx];
        int head = j * 2 + (lane >> 4);
        float4 t = __ldg((const float4*)(att + head * HID + (lane & 15) * 4));
        float vx = a.x + b.x; vx = vx > 0.f ? vx : 0.2f * vx;
        float vy = a.y + b.y; vy = vy > 0.f ? vy : 0.2f * vy;
        float vz = a.z + b.z; vz = vz > 0.f ? vz : 0.2f * vz;
        float vw = a.w + b.w; vw = vw > 0.f ? vw : 0.2f * vw;
        hsum[j] = vx * t.x + vy * t.y + vz * t.z + vw * t.w;
    }
    #pragma unroll
    for (int j = 0; j < 4; j++) {
        float v = hsum[j];
        v += __shfl_xor_sync(0xffffffffu, v, 1);
        v += __shfl_xor_sync(0xffffffffu, v, 2);
        v += __shfl_xor_sync(0xffffffffu, v, 4);
        v += __shfl_xor_sync(0xffffffffu, v, 8);
        hsum[j] = v;
    }
    if ((lane & 15) == 0) {
        int hi = lane >> 4;
        #pragma unroll
        for (int j = 0; j < 4; j++) {
            int head = j * 2 + hi;
            float w = expf(hsum[j]);
            exps[(long)e * HEADS + head] = w;
            atomicAdd(&expsum[(long)d * HEADS + head], w);
        }
    }
}

__global__ __launch_bounds__(256)
void edge_agg_h8(const float* __restrict__ xl,
                 const int* __restrict__ src, const int* __restrict__ dst,
                 const float* __restrict__ exps, const float* __restrict__ expsum,
                 float* __restrict__ acc)
{
    int e = blockIdx.x * 8 + (threadIdx.x >> 5);
    int lane = threadIdx.x & 31;
    int s = src[e], d = dst[e];
    float alpha0 = 0.f;
    if (lane < HEADS)
        alpha0 = exps[(long)e * HEADS + lane] / expsum[(long)d * HEADS + lane];
    const float4* pl = (const float4*)(xl + (long)s * DH);
    float* base = acc + (long)d * DH;
    #pragma unroll
    for (int j = 0; j < 4; j++) {
        int idx = j * 32 + lane;
        int head = j * 2 + (lane >> 4);
        float al = __shfl_sync(0xffffffffu, alpha0, head);
        float4 v = pl[idx];
        v.x *= al; v.y *= al; v.z *= al; v.w *= al;
        red_add_v4(base + idx * 4, v);
    }
}

// ---------------- layer 2 edge kernels (heads=1, ch=256) --------------------
__global__ __launch_bounds__(256)
void edge_scores_c256(const float* __restrict__ xl, const float* __restrict__ xr,
                      const int* __restrict__ src, const int* __restrict__ dst,
                      const float* __restrict__ att,  // [256]
                      float* __restrict__ exps, float* __restrict__ expsum)
{
    int e = blockIdx.x * 8 + (threadIdx.x >> 5);
    int lane = threadIdx.x & 31;
    int s = src[e], d = dst[e];
    const float4* pl = (const float4*)(xl + (long)s * DOUT);
    const float4* pr = (const float4*)(xr + (long)d * DOUT);
    float acc = 0.f;
    #pragma unroll
    for (int j = 0; j < 2; j++) {
        int idx = j * 32 + lane;
        float4 a = pl[idx];
        float4 b = pr[idx];
        float4 t = __ldg((const float4*)(att + idx * 4));
        float vx = a.x + b.x; vx = vx > 0.f ? vx : 0.2f * vx;
        float vy = a.y + b.y; vy = vy > 0.f ? vy : 0.2f * vy;
        float vz = a.z + b.z; vz = vz > 0.f ? vz : 0.2f * vz;
        float vw = a.w + b.w; vw = vw > 0.f ? vw : 0.2f * vw;
        acc += vx * t.x + vy * t.y + vz * t.z + vw * t.w;
    }
    acc = warp_sum(acc);
    if (lane == 0) {
        float w = expf(acc);
        exps[e] = w;
        atomicAdd(&expsum[d], w);
    }
}

__global__ __launch_bounds__(256)
void edge_agg_c256(const float* __restrict__ xl,
                   const int* __restrict__ src, const int* __restrict__ dst,
                   const float* __restrict__ exps, const float* __restrict__ expsum,
                   float* __restrict__ acc)
{
    int e = blockIdx.x * 8 + (threadIdx.x >> 5);
    int lane = threadIdx.x & 31;
    int s = src[e], d = dst[e];
    float alpha = exps[e] / expsum[d];
    const float4* pl = (const float4*)(xl + (long)s * DOUT);
    float* base = acc + (long)d * DOUT;
    #pragma unroll
    for (int j = 0; j < 2; j++) {
        int idx = j * 32 + lane;
        float4 v = pl[idx];
        v.x *= alpha; v.y *= alpha; v.z *= alpha; v.w *= alpha;
        red_add_v4(base + idx * 4, v);
    }
}

// ---------------- fused elementwise: elu + residual + layernorm -------------
__global__ __launch_bounds__(128)
void fuse_elu_res_ln512(const float* __restrict__ acc, const float* __restrict__ res,
                        const float* __restrict__ b0, const float* __restrict__ b1,
                        const float* __restrict__ b2,
                        const float* __restrict__ gamma, const float* __restrict__ beta,
                        float* __restrict__ out, __half* __restrict__ out16)
{
    int i = blockIdx.x;
    int t = threadIdx.x;
    float v[4];
    float s = 0.f, s2 = 0.f;
    #pragma unroll
    for (int j = 0; j < 4; j++) {
        int c = j * 128 + t;
        float x = acc[(long)i * DH + c] + b0[c] + b1[c] + b2[c];
        x = x > 0.f ? x : expm1f(x);
        x += res[(long)i * DH + c];
        v[j] = x; s += x; s2 += x * x;
    }
    s = warp_sum(s); s2 = warp_sum(s2);
    __shared__ float sh1[4], sh2[4];
    int w = t >> 5, l = t & 31;
    if (l == 0) { sh1[w] = s; sh2[w] = s2; }
    __syncthreads();
    s = sh1[0] + sh1[1] + sh1[2] + sh1[3];
    s2 = sh2[0] + sh2[1] + sh2[2] + sh2[3];
    float mu = s * (1.f / DH);
    float var = s2 * (1.f / DH) - mu * mu;
    float inv = rsqrtf(var + 1e-5f);
    #pragma unroll
    for (int j = 0; j < 4; j++) {
        int c = j * 128 + t;
        float o = (v[j] - mu) * inv * gamma[c] + beta[c];
        out[(long)i * DH + c] = o;
        out16[(long)i * DH + c] = __float2half_rn(o);
    }
}

__global__ __launch_bounds__(128)
void fuse_elu_ln256(const float* __restrict__ acc,
                    const float* __restrict__ b0, const float* __restrict__ b1,
                    const float* __restrict__ b2,
                    const float* __restrict__ gamma, const float* __restrict__ beta,
                    float* __restrict__ out)
{
    int i = blockIdx.x;
    int t = threadIdx.x;
    float v[2];
    float s = 0.f, s2 = 0.f;
    #pragma unroll
    for (int j = 0; j < 2; j++) {
        int c = j * 128 + t;
        float x = acc[(long)i * DOUT + c] + b0[c] + b1[c] + b2[c];
        x = x > 0.f ? x : expm1f(x);
        v[j] = x; s += x; s2 += x * x;
    }
    s = warp_sum(s); s2 = warp_sum(s2);
    __shared__ float sh1[4], sh2[4];
    int w = t >> 5, l = t & 31;
    if (l == 0) { sh1[w] = s; sh2[w] = s2; }
    __syncthreads();
    s = sh1[0] + sh1[1] + sh1[2] + sh1[3];
    s2 = sh2[0] + sh2[1] + sh2[2] + sh2[3];
    float mu = s * (1.f / DOUT);
    float var = s2 * (1.f / DOUT) - mu * mu;
    float inv = rsqrtf(var + 1e-5f);
    #pragma unroll
    for (int j = 0; j < 2; j++) {
        int c = j * 128 + t;
        out[(long)i * DOUT + c] = (v[j] - mu) * inv * gamma[c] + beta[c];
    }
}

// ---------------- host ------------------------------------------------------
static inline void run_gemm(const __half* A, const __half* B, const float* bias,
                            float* C, __half* C16, int M, int N, int K, int act)
{
    dim3 grid(N / GBN, (M + GBM - 1) / GBM);
    hgemm_bias_act<<<grid, 256>>>(A, B, bias, C, C16, M, N, K, act);
}

static inline void convert(const float* in, __half* out, long n)
{
    long n4 = n / 4;
    f32_to_f16<<<(unsigned)((n4 + 255) / 256), 256>>>(in, out, (int)n4);
}

extern "C" void kernel_launch(void* const* d_in, const int* in_sizes, int n_in,
                              void* d_out, int out_size)
{
    const float* x          = (const float*)d_in[0];
    const int*   edge_index = (const int*)  d_in[1];
    const float* proj_w     = (const float*)d_in[2];
    const float* proj_b     = (const float*)d_in[3];
    const float* l01_ll_w   = (const float*)d_in[4];
    const float* l01_ll_b   = (const float*)d_in[5];
    const float* l01_lr_w   = (const float*)d_in[6];
    const float* l01_lr_b   = (const float*)d_in[7];
    const float* l01_att    = (const float*)d_in[8];
    const float* l01_bias   = (const float*)d_in[9];
    const float* l2_ll_w    = (const float*)d_in[10];
    const float* l2_ll_b    = (const float*)d_in[11];
    const float* l2_lr_w    = (const float*)d_in[12];
    const float* l2_lr_b    = (const float*)d_in[13];
    const float* l2_att     = (const float*)d_in[14];
    const float* l2_bias    = (const float*)d_in[15];
    const float* ln01_gamma = (const float*)d_in[16];
    const float* ln01_beta  = (const float*)d_in[17];
    const float* ln2_gamma  = (const float*)d_in[18];
    const float* ln2_beta   = (const float*)d_in[19];

    float *h, *h2, *xl, *xr, *acc, *exps, *expsum;
    __half *a16, *x16, *w_proj, *w01l, *w01r, *w2l, *w2r;
    cudaGetSymbolAddress((void**)&h,      g_h);
    cudaGetSymbolAddress((void**)&h2,     g_h2);
    cudaGetSymbolAddress((void**)&xl,     g_xl);
    cudaGetSymbolAddress((void**)&xr,     g_xr);
    cudaGetSymbolAddress((void**)&acc,    g_acc);
    cudaGetSymbolAddress((void**)&exps,   g_exps);
    cudaGetSymbolAddress((void**)&expsum, g_expsum);
    cudaGetSymbolAddress((void**)&a16,    g_a16);
    cudaGetSymbolAddress((void**)&x16,    g_x16);
    cudaGetSymbolAddress((void**)&w_proj, g_w16_proj);
    cudaGetSymbolAddress((void**)&w01l,   g_w16_l01l);
    cudaGetSymbolAddress((void**)&w01r,   g_w16_l01r);
    cudaGetSymbolAddress((void**)&w2l,    g_w16_l2l);
    cudaGetSymbolAddress((void**)&w2r,    g_w16_l2r);

    // one-time fp16 conversions (cheap)
    convert(x, x16, (long)NN * DH);
    convert(proj_w, w_proj, (long)DH * DH);
    convert(l01_ll_w, w01l, (long)2 * 3 * DH * DH);
    convert(l01_lr_w, w01r, (long)2 * 3 * DH * DH);
    convert(l2_ll_w, w2l, (long)3 * DH * DOUT);
    convert(l2_lr_w, w2r, (long)3 * DH * DOUT);

    // input projection + ELU (fp32 out h, fp16 out a16)
    run_gemm(x16, w_proj, proj_b, h, a16, NN, DH, DH, 1);

    float* cur = h;
    float* nxt = h2;

    for (int li = 0; li < 2; li++) {
        cudaMemsetAsync(acc, 0, (size_t)NN * DH * sizeof(float));
        for (int et = 0; et < 3; et++) {
            const __half* Wl = w01l + ((size_t)(li * 3 + et)) * DH * DH;
            const float*  bl = l01_ll_b + (size_t)(li * 3 + et) * DH;
            const __half* Wr = w01r + ((size_t)(li * 3 + et)) * DH * DH;
            const float*  br = l01_lr_b + (size_t)(li * 3 + et) * DH;
            const float*  at = l01_att  + (size_t)(li * 3 + et) * HEADS * HID;
            const int* src = edge_index + (size_t)et * 2 * EE;
            const int* dst = src + EE;

            run_gemm(a16, Wl, bl, xl, nullptr, NN, DH, DH, 0);
            run_gemm(a16, Wr, br, xr, nullptr, NN, DH, DH, 0);
            cudaMemsetAsync(expsum, 0, (size_t)NN * HEADS * sizeof(float));
            edge_scores_h8<<<EE / 8, 256>>>(xl, xr, src, dst, at, exps, expsum);
            edge_agg_h8<<<EE / 8, 256>>>(xl, src, dst, exps, expsum, acc);
        }
        fuse_elu_res_ln512<<<NN, 128>>>(acc, cur,
                                        l01_bias + (size_t)(li * 3 + 0) * DH,
                                        l01_bias + (size_t)(li * 3 + 1) * DH,
                                        l01_bias + (size_t)(li * 3 + 2) * DH,
                                        ln01_gamma + (size_t)li * DH,
                                        ln01_beta  + (size_t)li * DH,
                                        nxt, a16);
        float* tmp = cur; cur = nxt; nxt = tmp;
    }

    // layer 2 (heads=1, out=256); reuse xl/xr/acc scratch
    cudaMemsetAsync(acc, 0, (size_t)NN * DOUT * sizeof(float));
    for (int et = 0; et < 3; et++) {
        const __half* Wl = w2l + (size_t)et * DH * DOUT;
        const float*  bl = l2_ll_b + (size_t)et * DOUT;
        const __half* Wr = w2r + (size_t)et * DH * DOUT;
        const float*  br = l2_lr_b + (size_t)et * DOUT;
        const float*  at = l2_att  + (size_t)et * DOUT;
        const int* src = edge_index + (size_t)et * 2 * EE;
        const int* dst = src + EE;

        run_gemm(a16, Wl, bl, xl, nullptr, NN, DOUT, DH, 0);
        run_gemm(a16, Wr, br, xr, nullptr, NN, DOUT, DH, 0);
        cudaMemsetAsync(expsum, 0, (size_t)NN * sizeof(float));
        edge_scores_c256<<<EE / 8, 256>>>(xl, xr, src, dst, at, exps, expsum);
        edge_agg_c256<<<EE / 8, 256>>>(xl, src, dst, exps, expsum, acc);
    }
    fuse_elu_ln256<<<NN, 128>>>(acc,
                                l2_bias + 0 * DOUT, l2_bias + 1 * DOUT, l2_bias + 2 * DOUT,
                                ln2_gamma, ln2_beta, (float*)d_out);
}

// round 5
// speedup vs baseline: 5.2420x; 1.0740x over previous
#include <cuda_runtime.h>
#include <cuda_fp16.h>
#include <stdint.h>
#include <math.h>

#define NN   20000
#define EE   100000
#define DH   512
#define DOUT 256
#define HEADS 8
#define HID  64

// ---------------- scratch (device globals; no allocations allowed) ----------
__device__ float g_h   [NN * DH];
__device__ float g_h2  [NN * DH];
__device__ float g_xcat[NN * 3072];            // batched GEMM output (xl|xr for 3 et)
__device__ float g_acc3[3 * NN * DH];          // per-relation aggregation
__device__ float g_zsum[3 * NN * HEADS];       // per-relation exp-sums

__device__ __half g_a16 [NN * DH];             // fp16 activation (GEMM A)
__device__ __half g_x16 [NN * DH];
__device__ __half g_w16_proj [DH * DH];
__device__ __half g_wcat01 [2 * DH * 3072];    // [li][k][ll0|ll1|ll2|lr0|lr1|lr2]
__device__ __half g_wcat2  [DH * 1536];        // [k][ll0|ll1|ll2|lr0|lr1|lr2]
__device__ float  g_bcat01 [2 * 3072];
__device__ float  g_bcat2  [1536];

// ---------------- converters / packers --------------------------------------
__global__ __launch_bounds__(256)
void f32_to_f16(const float* __restrict__ in, __half* __restrict__ out, int n4)
{
    int i = blockIdx.x * 256 + threadIdx.x;
    if (i >= n4) return;
    float4 v = ((const float4*)in)[i];
    union { __half2 h[2]; uint2 u; } p;
    p.h[0] = __floats2half2_rn(v.x, v.y);
    p.h[1] = __floats2half2_rn(v.z, v.w);
    ((uint2*)out)[i] = p.u;
}

__device__ __forceinline__ uint2 cvt4(float4 v) {
    union { __half2 h[2]; uint2 u; } p;
    p.h[0] = __floats2half2_rn(v.x, v.y);
    p.h[1] = __floats2half2_rn(v.z, v.w);
    return p.u;
}

// pack l01 weights: src [li][et][k][n] (ll and lr) -> dst [li][k][et*512+n | 1536+et*512+n]
__global__ __launch_bounds__(256)
void pack_w01(const float* __restrict__ ll, const float* __restrict__ lr,
              __half* __restrict__ out)
{
    int i = blockIdx.x * 256 + threadIdx.x;     // float4 index
    const int TOT = 2 * 3 * DH * DH / 4;        // 393216
    if (i >= TOT) return;
    int n4 = i & 127;
    int k  = (i >> 7) & 511;
    int le = i >> 16;                            // li*3+et
    int et = le % 3, li = le / 3;
    long base = ((long)li * DH + k) * 768;       // 3072/4
    ((uint2*)out)[base + et * 128 + n4]       = cvt4(((const float4*)ll)[i]);
    ((uint2*)out)[base + 384 + et * 128 + n4] = cvt4(((const float4*)lr)[i]);
}

// pack l2 weights: src [et][k][n] -> dst [k][et*256+n | 768+et*256+n]
__global__ __launch_bounds__(256)
void pack_w2(const float* __restrict__ ll, const float* __restrict__ lr,
             __half* __restrict__ out)
{
    int i = blockIdx.x * 256 + threadIdx.x;
    const int TOT = 3 * DH * DOUT / 4;           // 98304
    if (i >= TOT) return;
    int n4 = i & 63;
    int k  = (i >> 6) & 511;
    int et = i >> 15;
    long base = (long)k * 384;                   // 1536/4
    ((uint2*)out)[base + et * 64 + n4]       = cvt4(((const float4*)ll)[i]);
    ((uint2*)out)[base + 192 + et * 64 + n4] = cvt4(((const float4*)lr)[i]);
}

__global__ __launch_bounds__(256)
void pack_b01(const float* __restrict__ ll, const float* __restrict__ lr,
              float* __restrict__ out)
{
    int i = blockIdx.x * 256 + threadIdx.x;      // 2*3*512 = 3072
    if (i >= 2 * 3 * DH) return;
    int n = i & 511;
    int le = i >> 9;
    int et = le % 3, li = le / 3;
    out[li * 3072 + et * 512 + n]        = ll[i];
    out[li * 3072 + 1536 + et * 512 + n] = lr[i];
}

__global__ __launch_bounds__(256)
void pack_b2(const float* __restrict__ ll, const float* __restrict__ lr,
             float* __restrict__ out)
{
    int i = blockIdx.x * 256 + threadIdx.x;      // 3*256 = 768
    if (i >= 3 * DOUT) return;
    int n = i & 255;
    int et = i >> 8;
    out[et * 256 + n]       = ll[i];
    out[768 + et * 256 + n] = lr[i];
}

// ---------------- fp16 tensor-core GEMM (cp.async 2-stage pipeline) ---------
#define GBM 128
#define GBN 128
#define GBK 32
#define APAD 8
#define BPAD 8
#define A_STAGE_BYTES (GBM * (GBK + APAD) * 2)
#define B_STAGE_BYTES (GBK * (GBN + BPAD) * 2)

__device__ __forceinline__ uint32_t sptr(const void* p) {
    return (uint32_t)__cvta_generic_to_shared(p);
}
__device__ __forceinline__ void cp_async16(uint32_t dst, const void* src) {
    asm volatile("cp.async.cg.shared.global [%0], [%1], 16;" :: "r"(dst), "l"(src));
}
__device__ __forceinline__ void cp_commit() {
    asm volatile("cp.async.commit_group;");
}
template <int N> __device__ __forceinline__ void cp_wait() {
    asm volatile("cp.async.wait_group %0;" :: "n"(N));
}

__global__ __launch_bounds__(256)
void hgemm_bias_act(const __half* __restrict__ A, const __half* __restrict__ B,
                    const float* __restrict__ bias, float* __restrict__ C,
                    __half* __restrict__ C16, int M, int N, int K, int act)
{
    __shared__ __align__(16) __half As[2][GBM][GBK + APAD];
    __shared__ __align__(16) __half Bs[2][GBK][GBN + BPAD];

    int tid  = threadIdx.x;
    int lane = tid & 31;
    int wid  = tid >> 5;
    int m0 = (wid >> 2) * 64;
    int n0 = (wid & 3) * 32;
    int bx = blockIdx.x, by = blockIdx.y;

    int a_row0 = tid >> 2,  a_off0 = (tid & 3) * 8;
    int a_row1 = (tid + 256) >> 2, a_off1 = a_off0;
    int b_row0 = tid >> 4,  b_off0 = (tid & 15) * 8;
    int b_row1 = (tid + 256) >> 4, b_off1 = b_off0;

    uint32_t As0 = sptr(&As[0][0][0]);
    uint32_t Bs0 = sptr(&Bs[0][0][0]);

    float acc[4][4][4];
    #pragma unroll
    for (int mi = 0; mi < 4; mi++)
        #pragma unroll
        for (int ni = 0; ni < 4; ni++)
            #pragma unroll
            for (int r = 0; r < 4; r++) acc[mi][ni][r] = 0.f;

    uint32_t a_base[4];
    #pragma unroll
    for (int mi = 0; mi < 4; mi++)
        a_base[mi] = sptr(&As[0][m0 + mi * 16 + (lane & 15)][(lane >> 4) * 8]);
    uint32_t b_base[4];
    #pragma unroll
    for (int ni = 0; ni < 4; ni++)
        b_base[ni] = sptr(&Bs[0][lane & 15][n0 + ni * 8]);

    int gr0 = by * GBM + a_row0; if (gr0 >= M) gr0 = M - 1;
    int gr1 = by * GBM + a_row1; if (gr1 >= M) gr1 = M - 1;

    {
        cp_async16(As0 + a_row0 * 80 + a_off0 * 2, A + (long)gr0 * K + a_off0);
        cp_async16(As0 + a_row1 * 80 + a_off1 * 2, A + (long)gr1 * K + a_off1);
        cp_async16(Bs0 + b_row0 * 272 + b_off0 * 2, B + (long)b_row0 * N + bx * GBN + b_off0);
        cp_async16(Bs0 + b_row1 * 272 + b_off1 * 2, B + (long)b_row1 * N + bx * GBN + b_off1);
        cp_commit();
    }

    int iters = K / GBK;
    for (int it = 0; it < iters; it++) {
        if (it + 1 < iters) {
            int k0 = (it + 1) * GBK;
            int st = (it + 1) & 1;
            uint32_t Ad = As0 + st * A_STAGE_BYTES;
            uint32_t Bd = Bs0 + st * B_STAGE_BYTES;
            cp_async16(Ad + a_row0 * 80 + a_off0 * 2, A + (long)gr0 * K + k0 + a_off0);
            cp_async16(Ad + a_row1 * 80 + a_off1 * 2, A + (long)gr1 * K + k0 + a_off1);
            cp_async16(Bd + b_row0 * 272 + b_off0 * 2, B + (long)(k0 + b_row0) * N + bx * GBN + b_off0);
            cp_async16(Bd + b_row1 * 272 + b_off1 * 2, B + (long)(k0 + b_row1) * N + bx * GBN + b_off1);
            cp_commit();
            cp_wait<1>();
        } else {
            cp_wait<0>();
        }
        __syncthreads();

        int st = it & 1;
        uint32_t aofs = st * A_STAGE_BYTES;
        uint32_t bofs = st * B_STAGE_BYTES;
        #pragma unroll
        for (int ks = 0; ks < GBK; ks += 16) {
            uint32_t af[4][4], bf[4][2];
            #pragma unroll
            for (int mi = 0; mi < 4; mi++) {
                asm volatile("ldmatrix.sync.aligned.m8n8.x4.shared.b16 {%0,%1,%2,%3}, [%4];"
                             : "=r"(af[mi][0]), "=r"(af[mi][1]), "=r"(af[mi][2]), "=r"(af[mi][3])
                             : "r"(a_base[mi] + aofs + ks * 2));
            }
            #pragma unroll
            for (int ni = 0; ni < 4; ni++) {
                asm volatile("ldmatrix.sync.aligned.m8n8.x2.trans.shared.b16 {%0,%1}, [%2];"
                             : "=r"(bf[ni][0]), "=r"(bf[ni][1])
                             : "r"(b_base[ni] + bofs + ks * (GBN + BPAD) * 2));
            }
            #pragma unroll
            for (int mi = 0; mi < 4; mi++)
                #pragma unroll
                for (int ni = 0; ni < 4; ni++) {
                    asm volatile(
                        "mma.sync.aligned.m16n8k16.row.col.f32.f16.f16.f32 "
                        "{%0,%1,%2,%3},{%4,%5,%6,%7},{%8,%9},{%0,%1,%2,%3};"
                        : "+f"(acc[mi][ni][0]), "+f"(acc[mi][ni][1]),
                          "+f"(acc[mi][ni][2]), "+f"(acc[mi][ni][3])
                        : "r"(af[mi][0]), "r"(af[mi][1]), "r"(af[mi][2]), "r"(af[mi][3]),
                          "r"(bf[ni][0]), "r"(bf[ni][1]));
                }
        }
        __syncthreads();
    }

    #pragma unroll
    for (int mi = 0; mi < 4; mi++) {
        int r0 = by * GBM + m0 + mi * 16 + (lane >> 2);
        #pragma unroll
        for (int ni = 0; ni < 4; ni++) {
            int c = bx * GBN + n0 + ni * 8 + (lane & 3) * 2;
            float bx0 = bias[c], bx1 = bias[c + 1];
            #pragma unroll
            for (int half_ = 0; half_ < 2; half_++) {
                int r = r0 + half_ * 8;
                if (r >= M) continue;
                float v0 = acc[mi][ni][half_ * 2 + 0] + bx0;
                float v1 = acc[mi][ni][half_ * 2 + 1] + bx1;
                if (act) {
                    v0 = v0 > 0.f ? v0 : expm1f(v0);
                    v1 = v1 > 0.f ? v1 : expm1f(v1);
                }
                *(float2*)(C + (long)r * N + c) = make_float2(v0, v1);
                if (C16)
                    *(__half2*)(C16 + (long)r * N + c) = __floats2half2_rn(v0, v1);
            }
        }
    }
}

// ---------------- helpers ---------------------------------------------------
__device__ __forceinline__ float warp_sum(float v) {
    #pragma unroll
    for (int o = 16; o; o >>= 1) v += __shfl_xor_sync(0xffffffffu, v, o);
    return v;
}

__device__ __forceinline__ void red_add_v4(float* p, float4 v) {
    asm volatile("red.global.add.v4.f32 [%0], {%1,%2,%3,%4};"
                 :: "l"(p), "f"(v.x), "f"(v.y), "f"(v.z), "f"(v.w) : "memory");
}

// ---------------- fused edge pass, layers 0/1 -------------------------------
// warp per edge. xl/xr rows live in xcat (stride 3072). score -> w=exp ->
// red_add(w*xl) + red_add(w) [deferred normalization].
__global__ __launch_bounds__(256)
void edge_fused_h8(const float* __restrict__ xl, const float* __restrict__ xr,
                   const int* __restrict__ src, const int* __restrict__ dst,
                   const float* __restrict__ att,   // [8,64]
                   float* __restrict__ acc, float* __restrict__ zsum)
{
    int e = blockIdx.x * 8 + (threadIdx.x >> 5);
    int lane = threadIdx.x & 31;
    int s = src[e], d = dst[e];
    const float4* pl = (const float4*)(xl + (long)s * 3072);
    const float4* pr = (const float4*)(xr + (long)d * 3072);
    float* accd = acc + (long)d * DH;
    #pragma unroll
    for (int j = 0; j < 4; j++) {
        int idx = j * 32 + lane;
        float4 a = pl[idx];
        float4 b = pr[idx];
        int head = j * 2 + (lane >> 4);
        float4 t = __ldg((const float4*)(att + head * HID + (lane & 15) * 4));
        float vx = a.x + b.x; vx = vx > 0.f ? vx : 0.2f * vx;
        float vy = a.y + b.y; vy = vy > 0.f ? vy : 0.2f * vy;
        float vz = a.z + b.z; vz = vz > 0.f ? vz : 0.2f * vz;
        float vw = a.w + b.w; vw = vw > 0.f ? vw : 0.2f * vw;
        float p = vx * t.x + vy * t.y + vz * t.z + vw * t.w;
        p += __shfl_xor_sync(0xffffffffu, p, 1);
        p += __shfl_xor_sync(0xffffffffu, p, 2);
        p += __shfl_xor_sync(0xffffffffu, p, 4);
        p += __shfl_xor_sync(0xffffffffu, p, 8);
        float w = expf(p);
        if ((lane & 15) == 0)
            atomicAdd(&zsum[(long)d * HEADS + head], w);
        a.x *= w; a.y *= w; a.z *= w; a.w *= w;
        red_add_v4(accd + idx * 4, a);
    }
}

// ---------------- fused edge pass, layer 2 (heads=1, ch=256) ----------------
__global__ __launch_bounds__(256)
void edge_fused_c256(const float* __restrict__ xl, const float* __restrict__ xr,
                     const int* __restrict__ src, const int* __restrict__ dst,
                     const float* __restrict__ att,   // [256]
                     float* __restrict__ acc, float* __restrict__ zsum)
{
    int e = blockIdx.x * 8 + (threadIdx.x >> 5);
    int lane = threadIdx.x & 31;
    int s = src[e], d = dst[e];
    const float4* pl = (const float4*)(xl + (long)s * 1536);
    const float4* pr = (const float4*)(xr + (long)d * 1536);
    float4 a0 = pl[lane],     a1 = pl[32 + lane];
    float4 b0 = pr[lane],     b1 = pr[32 + lane];
    float4 t0 = __ldg((const float4*)(att + lane * 4));
    float4 t1 = __ldg((const float4*)(att + 128 + lane * 4));
    float p;
    {
        float vx = a0.x + b0.x; vx = vx > 0.f ? vx : 0.2f * vx;
        float vy = a0.y + b0.y; vy = vy > 0.f ? vy : 0.2f * vy;
        float vz = a0.z + b0.z; vz = vz > 0.f ? vz : 0.2f * vz;
        float vw = a0.w + b0.w; vw = vw > 0.f ? vw : 0.2f * vw;
        p = vx * t0.x + vy * t0.y + vz * t0.z + vw * t0.w;
        vx = a1.x + b1.x; vx = vx > 0.f ? vx : 0.2f * vx;
        vy = a1.y + b1.y; vy = vy > 0.f ? vy : 0.2f * vy;
        vz = a1.z + b1.z; vz = vz > 0.f ? vz : 0.2f * vz;
        vw = a1.w + b1.w; vw = vw > 0.f ? vw : 0.2f * vw;
        p += vx * t1.x + vy * t1.y + vz * t1.z + vw * t1.w;
    }
    p = warp_sum(p);
    float w = expf(p);
    if (lane == 0) atomicAdd(&zsum[d], w);
    float* accd = acc + (long)d * DOUT;
    a0.x *= w; a0.y *= w; a0.z *= w; a0.w *= w;
    a1.x *= w; a1.y *= w; a1.z *= w; a1.w *= w;
    red_add_v4(accd + lane * 4, a0);
    red_add_v4(accd + 128 + lane * 4, a1);
}

// ---------------- fused: normalize + bias + elu + residual + layernorm ------
__global__ __launch_bounds__(128)
void fuse_l01(const float* __restrict__ acc3, const float* __restrict__ z3,
              const float* __restrict__ b0, const float* __restrict__ b1,
              const float* __restrict__ b2,
              const float* __restrict__ res,
              const float* __restrict__ gamma, const float* __restrict__ beta,
              float* __restrict__ out, __half* __restrict__ out16)
{
    int i = blockIdx.x;
    int t = threadIdx.x;
    // per-et reciprocal z for the heads this thread touches
    float v[4];
    float s = 0.f, s2 = 0.f;
    #pragma unroll
    for (int j = 0; j < 4; j++) {
        int c = j * 128 + t;
        int head = c >> 6;
        float x = b0[c] + b1[c] + b2[c];
        #pragma unroll
        for (int et = 0; et < 3; et++) {
            float z = z3[(long)et * NN * HEADS + (long)i * HEADS + head];
            float rz = z != 0.f ? 1.f / z : 0.f;
            x += acc3[(long)et * NN * DH + (long)i * DH + c] * rz;
        }
        x = x > 0.f ? x : expm1f(x);
        x += res[(long)i * DH + c];
        v[j] = x; s += x; s2 += x * x;
    }
    s = warp_sum(s); s2 = warp_sum(s2);
    __shared__ float sh1[4], sh2[4];
    int w = t >> 5, l = t & 31;
    if (l == 0) { sh1[w] = s; sh2[w] = s2; }
    __syncthreads();
    s = sh1[0] + sh1[1] + sh1[2] + sh1[3];
    s2 = sh2[0] + sh2[1] + sh2[2] + sh2[3];
    float mu = s * (1.f / DH);
    float var = s2 * (1.f / DH) - mu * mu;
    float inv = rsqrtf(var + 1e-5f);
    #pragma unroll
    for (int j = 0; j < 4; j++) {
        int c = j * 128 + t;
        float o = (v[j] - mu) * inv * gamma[c] + beta[c];
        out[(long)i * DH + c] = o;
        out16[(long)i * DH + c] = __float2half_rn(o);
    }
}

__global__ __launch_bounds__(128)
void fuse_l2(const float* __restrict__ acc3, const float* __restrict__ z3,
             const float* __restrict__ b0, const float* __restrict__ b1,
             const float* __restrict__ b2,
             const float* __restrict__ gamma, const float* __restrict__ beta,
             float* __restrict__ out)
{
    int i = blockIdx.x;
    int t = threadIdx.x;
    float rz[3];
    #pragma unroll
    for (int et = 0; et < 3; et++) {
        float z = z3[(long)et * NN + i];
        rz[et] = z != 0.f ? 1.f / z : 0.f;
    }
    float v[2];
    float s = 0.f, s2 = 0.f;
    #pragma unroll
    for (int j = 0; j < 2; j++) {
        int c = j * 128 + t;
        float x = b0[c] + b1[c] + b2[c];
        #pragma unroll
        for (int et = 0; et < 3; et++)
            x += acc3[(long)et * NN * DOUT + (long)i * DOUT + c] * rz[et];
        x = x > 0.f ? x : expm1f(x);
        v[j] = x; s += x; s2 += x * x;
    }
    s = warp_sum(s); s2 = warp_sum(s2);
    __shared__ float sh1[4], sh2[4];
    int w = t >> 5, l = t & 31;
    if (l == 0) { sh1[w] = s; sh2[w] = s2; }
    __syncthreads();
    s = sh1[0] + sh1[1] + sh1[2] + sh1[3];
    s2 = sh2[0] + sh2[1] + sh2[2] + sh2[3];
    float mu = s * (1.f / DOUT);
    float var = s2 * (1.f / DOUT) - mu * mu;
    float inv = rsqrtf(var + 1e-5f);
    #pragma unroll
    for (int j = 0; j < 2; j++) {
        int c = j * 128 + t;
        out[(long)i * DOUT + c] = (v[j] - mu) * inv * gamma[c] + beta[c];
    }
}

// ---------------- host ------------------------------------------------------
static inline void run_gemm(const __half* A, const __half* B, const float* bias,
                            float* C, __half* C16, int M, int N, int K, int act)
{
    dim3 grid(N / GBN, (M + GBM - 1) / GBM);
    hgemm_bias_act<<<grid, 256>>>(A, B, bias, C, C16, M, N, K, act);
}

static inline void convert(const float* in, __half* out, long n)
{
    long n4 = n / 4;
    f32_to_f16<<<(unsigned)((n4 + 255) / 256), 256>>>(in, out, (int)n4);
}

extern "C" void kernel_launch(void* const* d_in, const int* in_sizes, int n_in,
                              void* d_out, int out_size)
{
    const float* x          = (const float*)d_in[0];
    const int*   edge_index = (const int*)  d_in[1];
    const float* proj_w     = (const float*)d_in[2];
    const float* proj_b     = (const float*)d_in[3];
    const float* l01_ll_w   = (const float*)d_in[4];
    const float* l01_ll_b   = (const float*)d_in[5];
    const float* l01_lr_w   = (const float*)d_in[6];
    const float* l01_lr_b   = (const float*)d_in[7];
    const float* l01_att    = (const float*)d_in[8];
    const float* l01_bias   = (const float*)d_in[9];
    const float* l2_ll_w    = (const float*)d_in[10];
    const float* l2_ll_b    = (const float*)d_in[11];
    const float* l2_lr_w    = (const float*)d_in[12];
    const float* l2_lr_b    = (const float*)d_in[13];
    const float* l2_att     = (const float*)d_in[14];
    const float* l2_bias    = (const float*)d_in[15];
    const float* ln01_gamma = (const float*)d_in[16];
    const float* ln01_beta  = (const float*)d_in[17];
    const float* ln2_gamma  = (const float*)d_in[18];
    const float* ln2_beta   = (const float*)d_in[19];

    float *h, *h2, *xcat, *acc3, *zsum, *bcat01, *bcat2;
    __half *a16, *x16, *w_proj, *wcat01, *wcat2;
    cudaGetSymbolAddress((void**)&h,      g_h);
    cudaGetSymbolAddress((void**)&h2,     g_h2);
    cudaGetSymbolAddress((void**)&xcat,   g_xcat);
    cudaGetSymbolAddress((void**)&acc3,   g_acc3);
    cudaGetSymbolAddress((void**)&zsum,   g_zsum);
    cudaGetSymbolAddress((void**)&a16,    g_a16);
    cudaGetSymbolAddress((void**)&x16,    g_x16);
    cudaGetSymbolAddress((void**)&w_proj, g_w16_proj);
    cudaGetSymbolAddress((void**)&wcat01, g_wcat01);
    cudaGetSymbolAddress((void**)&wcat2,  g_wcat2);
    cudaGetSymbolAddress((void**)&bcat01, g_bcat01);
    cudaGetSymbolAddress((void**)&bcat2,  g_bcat2);

    // one-time conversions / packs
    convert(x, x16, (long)NN * DH);
    convert(proj_w, w_proj, (long)DH * DH);
    pack_w01<<<(2 * 3 * DH * DH / 4 + 255) / 256, 256>>>(l01_ll_w, l01_lr_w, wcat01);
    pack_w2 <<<(3 * DH * DOUT / 4 + 255) / 256, 256>>>(l2_ll_w, l2_lr_w, wcat2);
    pack_b01<<<(2 * 3 * DH + 255) / 256, 256>>>(l01_ll_b, l01_lr_b, bcat01);
    pack_b2 <<<(3 * DOUT + 255) / 256, 256>>>(l2_ll_b, l2_lr_b, bcat2);

    // input projection + ELU (fp32 out h, fp16 out a16)
    run_gemm(x16, w_proj, proj_b, h, a16, NN, DH, DH, 1);

    float* cur = h;
    float* nxt = h2;

    for (int li = 0; li < 2; li++) {
        cudaMemsetAsync(acc3, 0, (size_t)3 * NN * DH * sizeof(float));
        cudaMemsetAsync(zsum, 0, (size_t)3 * NN * HEADS * sizeof(float));
        // one batched GEMM: [20000x512] x [512x3072] -> xcat
        run_gemm(a16, wcat01 + (size_t)li * DH * 3072, bcat01 + (size_t)li * 3072,
                 xcat, nullptr, NN, 3072, DH, 0);
        for (int et = 0; et < 3; et++) {
            const int* src = edge_index + (size_t)et * 2 * EE;
            const int* dst = src + EE;
            edge_fused_h8<<<EE / 8, 256>>>(
                xcat + (size_t)et * 512, xcat + 1536 + (size_t)et * 512,
                src, dst,
                l01_att + (size_t)(li * 3 + et) * HEADS * HID,
                acc3 + (size_t)et * NN * DH,
                zsum + (size_t)et * NN * HEADS);
        }
        fuse_l01<<<NN, 128>>>(acc3, zsum,
                              l01_bias + (size_t)(li * 3 + 0) * DH,
                              l01_bias + (size_t)(li * 3 + 1) * DH,
                              l01_bias + (size_t)(li * 3 + 2) * DH,
                              cur,
                              ln01_gamma + (size_t)li * DH,
                              ln01_beta  + (size_t)li * DH,
                              nxt, a16);
        float* tmp = cur; cur = nxt; nxt = tmp;
    }

    // layer 2 (heads=1, out=256)
    cudaMemsetAsync(acc3, 0, (size_t)3 * NN * DOUT * sizeof(float));
    cudaMemsetAsync(zsum, 0, (size_t)3 * NN * sizeof(float));
    run_gemm(a16, wcat2, bcat2, xcat, nullptr, NN, 1536, DH, 0);
    for (int et = 0; et < 3; et++) {
        const int* src = edge_index + (size_t)et * 2 * EE;
        const int* dst = src + EE;
        edge_fused_c256<<<EE / 8, 256>>>(
            xcat + (size_t)et * 256, xcat + 768 + (size_t)et * 256,
            src, dst,
            l2_att + (size_t)et * DOUT,
            acc3 + (size_t)et * NN * DOUT,
            zsum + (size_t)et * NN);
    }
    fuse_l2<<<NN, 128>>>(acc3, zsum,
                         l2_bias + 0 * DOUT, l2_bias + 1 * DOUT, l2_bias + 2 * DOUT,
                         ln2_gamma, ln2_beta, (float*)d_out);
}

// round 7
// speedup vs baseline: 5.5394x; 1.0567x over previous
#include <cuda_runtime.h>
#include <cuda_fp16.h>
#include <stdint.h>
#include <math.h>

#define NN   20000
#define EE   100000
#define DH   512
#define DOUT 256
#define HEADS 8
#define HID  64

// ---------------- scratch (device globals; no allocations allowed) ----------
__device__ float g_h   [NN * DH];
__device__ float g_h2  [NN * DH];
__device__ float g_xcat[NN * 3072];            // batched GEMM output (xl|xr for 3 et)
__device__ float g_acc3[3 * NN * DH];          // per-relation aggregation
__device__ float g_zsum[3 * NN * HEADS];       // per-relation exp-sums

__device__ __half g_a16 [NN * DH];             // fp16 activation (GEMM A)
__device__ __half g_x16 [NN * DH];
__device__ __half g_w16_proj [DH * DH];
__device__ __half g_wcat01 [2 * DH * 3072];    // [li][k][ll0|ll1|ll2|lr0|lr1|lr2]
__device__ __half g_wcat2  [DH * 1536];        // [k][ll0|ll1|ll2|lr0|lr1|lr2]
__device__ float  g_bcat01 [2 * 3072];
__device__ float  g_bcat2  [1536];

// ---------------- converters / packers --------------------------------------
__global__ __launch_bounds__(256)
void f32_to_f16(const float* __restrict__ in, __half* __restrict__ out, int n4)
{
    int i = blockIdx.x * 256 + threadIdx.x;
    if (i >= n4) return;
    float4 v = ((const float4*)in)[i];
    union { __half2 h[2]; uint2 u; } p;
    p.h[0] = __floats2half2_rn(v.x, v.y);
    p.h[1] = __floats2half2_rn(v.z, v.w);
    ((uint2*)out)[i] = p.u;
}

__device__ __forceinline__ uint2 cvt4(float4 v) {
    union { __half2 h[2]; uint2 u; } p;
    p.h[0] = __floats2half2_rn(v.x, v.y);
    p.h[1] = __floats2half2_rn(v.z, v.w);
    return p.u;
}

// pack l01 weights: src [li][et][k][n] -> dst [li][k][et*512+n | 1536+et*512+n]
__global__ __launch_bounds__(256)
void pack_w01(const float* __restrict__ ll, const float* __restrict__ lr,
              __half* __restrict__ out)
{
    int i = blockIdx.x * 256 + threadIdx.x;     // float4 index
    const int TOT = 2 * 3 * DH * DH / 4;        // 393216
    if (i >= TOT) return;
    int n4 = i & 127;
    int k  = (i >> 7) & 511;
    int le = i >> 16;                            // li*3+et
    int et = le % 3, li = le / 3;
    long base = ((long)li * DH + k) * 768;       // 3072/4
    ((uint2*)out)[base + et * 128 + n4]       = cvt4(((const float4*)ll)[i]);
    ((uint2*)out)[base + 384 + et * 128 + n4] = cvt4(((const float4*)lr)[i]);
}

// pack l2 weights: src [et][k][n] -> dst [k][et*256+n | 768+et*256+n]
__global__ __launch_bounds__(256)
void pack_w2(const float* __restrict__ ll, const float* __restrict__ lr,
             __half* __restrict__ out)
{
    int i = blockIdx.x * 256 + threadIdx.x;
    const int TOT = 3 * DH * DOUT / 4;           // 98304
    if (i >= TOT) return;
    int n4 = i & 63;
    int k  = (i >> 6) & 511;
    int et = i >> 15;
    long base = (long)k * 384;                   // 1536/4
    ((uint2*)out)[base + et * 64 + n4]       = cvt4(((const float4*)ll)[i]);
    ((uint2*)out)[base + 192 + et * 64 + n4] = cvt4(((const float4*)lr)[i]);
}

__global__ __launch_bounds__(256)
void pack_b01(const float* __restrict__ ll, const float* __restrict__ lr,
              float* __restrict__ out)
{
    int i = blockIdx.x * 256 + threadIdx.x;      // 2*3*512 = 3072
    if (i >= 2 * 3 * DH) return;
    int n = i & 511;
    int le = i >> 9;
    int et = le % 3, li = le / 3;
    out[li * 3072 + et * 512 + n]        = ll[i];
    out[li * 3072 + 1536 + et * 512 + n] = lr[i];
}

__global__ __launch_bounds__(256)
void pack_b2(const float* __restrict__ ll, const float* __restrict__ lr,
             float* __restrict__ out)
{
    int i = blockIdx.x * 256 + threadIdx.x;      // 3*256 = 768
    if (i >= 3 * DOUT) return;
    int n = i & 255;
    int et = i >> 8;
    out[et * 256 + n]       = ll[i];
    out[768 + et * 256 + n] = lr[i];
}

// ---------------- fp16 HMMA GEMM, single-sync pipelined ---------------------
// C = act(A[Mx512] * B[512xN] + bias). A,B fp16 row-major. K fixed at 512.
// Block 128x128, GBK=64, 2 dynamic-SMEM stages, 1 __syncthreads per k-iter,
// cp.async for stage i+1 issued before the MMA block of stage i.

#define GBM 128
#define GBN 128
#define GBK 64
#define KFIX 512
#define KITERS (KFIX / GBK)        // 8
#define A_ROWB 144                 // (64+8) halves
#define B_ROWB 272                 // (128+8) halves
#define A_STAGE (GBM * A_ROWB)     // 18432 B
#define B_STAGE (GBK * B_ROWB)     // 17408 B
#define GEMM_SMEM (2 * (A_STAGE + B_STAGE))   // 71680 B

__device__ __forceinline__ uint32_t sptr(const void* p) {
    return (uint32_t)__cvta_generic_to_shared(p);
}
__device__ __forceinline__ void cp_async16(uint32_t dst, const void* src) {
    asm volatile("cp.async.cg.shared.global [%0], [%1], 16;" :: "r"(dst), "l"(src));
}
__device__ __forceinline__ void cp_commit() { asm volatile("cp.async.commit_group;"); }
template <int N> __device__ __forceinline__ void cp_wait() {
    asm volatile("cp.async.wait_group %0;" :: "n"(N));
}

__global__ __launch_bounds__(256, 2)
void hgemm_bias_act(const __half* __restrict__ A, const __half* __restrict__ B,
                    const float* __restrict__ bias, float* __restrict__ C,
                    __half* __restrict__ C16, int M, int N, int act)
{
    extern __shared__ char dsm[];
    uint32_t sA = sptr(dsm);                   // stage s at sA + s*A_STAGE
    uint32_t sB = sA + 2 * A_STAGE;            // stage s at sB + s*B_STAGE

    int tid  = threadIdx.x;
    int lane = tid & 31;
    int wid  = tid >> 5;
    int m0 = (wid >> 2) * 64;
    int n0 = (wid & 3) * 32;
    int bx = blockIdx.x, by = blockIdx.y;

    // cp.async mapping: 1024 16B chunks per operand per stage, 4 per thread
    int arow[4], aofs[4], gr[4], brow[4], bofs[4];
    #pragma unroll
    for (int i = 0; i < 4; i++) {
        int ch = tid + i * 256;
        arow[i] = ch >> 3;            // 0..127
        aofs[i] = (ch & 7) * 8;       // half offset in 64-half row
        int r = by * GBM + arow[i];
        gr[i] = r < M ? r : M - 1;
        brow[i] = ch >> 4;            // 0..63
        bofs[i] = (ch & 15) * 8;      // half offset in 128-half row
    }

    float acc[4][4][4];
    #pragma unroll
    for (int mi = 0; mi < 4; mi++)
        #pragma unroll
        for (int ni = 0; ni < 4; ni++)
            #pragma unroll
            for (int r = 0; r < 4; r++) acc[mi][ni][r] = 0.f;

    // ldmatrix base addresses (stage 0)
    uint32_t a_base[4];
    #pragma unroll
    for (int mi = 0; mi < 4; mi++)
        a_base[mi] = sA + (m0 + mi * 16 + (lane & 15)) * A_ROWB + (lane >> 4) * 16;
    uint32_t b_base[4];
    #pragma unroll
    for (int ni = 0; ni < 4; ni++)
        b_base[ni] = sB + (lane & 15) * B_ROWB + (n0 + ni * 8) * 2;

    // prologue: stage k-chunk 0 into buffer 0
    #pragma unroll
    for (int i = 0; i < 4; i++) {
        cp_async16(sA + arow[i] * A_ROWB + aofs[i] * 2,
                   A + (long)gr[i] * KFIX + aofs[i]);
        cp_async16(sB + brow[i] * B_ROWB + bofs[i] * 2,
                   B + (long)brow[i] * N + bx * GBN + bofs[i]);
    }
    cp_commit();

    for (int it = 0; it < KITERS; it++) {
        cp_wait<0>();
        __syncthreads();
        if (it + 1 < KITERS) {
            int k0 = (it + 1) * GBK;
            int st = (it + 1) & 1;
            uint32_t dA = sA + st * A_STAGE;
            uint32_t dB = sB + st * B_STAGE;
            #pragma unroll
            for (int i = 0; i < 4; i++) {
                cp_async16(dA + arow[i] * A_ROWB + aofs[i] * 2,
                           A + (long)gr[i] * KFIX + k0 + aofs[i]);
                cp_async16(dB + brow[i] * B_ROWB + bofs[i] * 2,
                           B + (long)(k0 + brow[i]) * N + bx * GBN + bofs[i]);
            }
            cp_commit();
        }

        int st = it & 1;
        uint32_t aofs_st = st * A_STAGE;
        uint32_t bofs_st = st * B_STAGE;
        #pragma unroll
        for (int ks = 0; ks < GBK; ks += 16) {
            uint32_t af[4][4], bf[4][2];
            #pragma unroll
            for (int mi = 0; mi < 4; mi++) {
                asm volatile("ldmatrix.sync.aligned.m8n8.x4.shared.b16 {%0,%1,%2,%3}, [%4];"
                             : "=r"(af[mi][0]), "=r"(af[mi][1]), "=r"(af[mi][2]), "=r"(af[mi][3])
                             : "r"(a_base[mi] + aofs_st + ks * 2));
            }
            #pragma unroll
            for (int ni = 0; ni < 4; ni++) {
                asm volatile("ldmatrix.sync.aligned.m8n8.x2.trans.shared.b16 {%0,%1}, [%2];"
                             : "=r"(bf[ni][0]), "=r"(bf[ni][1])
                             : "r"(b_base[ni] + bofs_st + ks * B_ROWB));
            }
            #pragma unroll
            for (int mi = 0; mi < 4; mi++)
                #pragma unroll
                for (int ni = 0; ni < 4; ni++) {
                    asm volatile(
                        "mma.sync.aligned.m16n8k16.row.col.f32.f16.f16.f32 "
                        "{%0,%1,%2,%3},{%4,%5,%6,%7},{%8,%9},{%0,%1,%2,%3};"
                        : "+f"(acc[mi][ni][0]), "+f"(acc[mi][ni][1]),
                          "+f"(acc[mi][ni][2]), "+f"(acc[mi][ni][3])
                        : "r"(af[mi][0]), "r"(af[mi][1]), "r"(af[mi][2]), "r"(af[mi][3]),
                          "r"(bf[ni][0]), "r"(bf[ni][1]));
                }
        }
    }

    // epilogue
    #pragma unroll
    for (int mi = 0; mi < 4; mi++) {
        int r0 = by * GBM + m0 + mi * 16 + (lane >> 2);
        #pragma unroll
        for (int ni = 0; ni < 4; ni++) {
            int c = bx * GBN + n0 + ni * 8 + (lane & 3) * 2;
            float bx0 = bias[c], bx1 = bias[c + 1];
            #pragma unroll
            for (int half_ = 0; half_ < 2; half_++) {
                int r = r0 + half_ * 8;
                if (r >= M) continue;
                float v0 = acc[mi][ni][half_ * 2 + 0] + bx0;
                float v1 = acc[mi][ni][half_ * 2 + 1] + bx1;
                if (act) {
                    v0 = v0 > 0.f ? v0 : expm1f(v0);
                    v1 = v1 > 0.f ? v1 : expm1f(v1);
                }
                *(float2*)(C + (long)r * N + c) = make_float2(v0, v1);
                if (C16)
                    *(__half2*)(C16 + (long)r * N + c) = __floats2half2_rn(v0, v1);
            }
        }
    }
}

// ---------------- helpers ---------------------------------------------------
__device__ __forceinline__ float warp_sum(float v) {
    #pragma unroll
    for (int o = 16; o; o >>= 1) v += __shfl_xor_sync(0xffffffffu, v, o);
    return v;
}
__device__ __forceinline__ void red_add_v4(float* p, float4 v) {
    asm volatile("red.global.add.v4.f32 [%0], {%1,%2,%3,%4};"
                 :: "l"(p), "f"(v.x), "f"(v.y), "f"(v.z), "f"(v.w) : "memory");
}

// ---------------- fused edge pass, layers 0/1 -------------------------------
__global__ __launch_bounds__(256)
void edge_fused_h8(const float* __restrict__ xl, const float* __restrict__ xr,
                   const int* __restrict__ src, const int* __restrict__ dst,
                   const float* __restrict__ att,
                   float* __restrict__ acc, float* __restrict__ zsum)
{
    int e = blockIdx.x * 8 + (threadIdx.x >> 5);
    int lane = threadIdx.x & 31;
    int s = src[e], d = dst[e];
    const float4* pl = (const float4*)(xl + (long)s * 3072);
    const float4* pr = (const float4*)(xr + (long)d * 3072);
    float* accd = acc + (long)d * DH;
    #pragma unroll
    for (int j = 0; j < 4; j++) {
        int idx = j * 32 + lane;
        float4 a = pl[idx];
        float4 b = pr[idx];
        int head = j * 2 + (lane >> 4);
        float4 t = __ldg((const float4*)(att + head * HID + (lane & 15) * 4));
        float vx = a.x + b.x; vx = vx > 0.f ? vx : 0.2f * vx;
        float vy = a.y + b.y; vy = vy > 0.f ? vy : 0.2f * vy;
        float vz = a.z + b.z; vz = vz > 0.f ? vz : 0.2f * vz;
        float vw = a.w + b.w; vw = vw > 0.f ? vw : 0.2f * vw;
        float p = vx * t.x + vy * t.y + vz * t.z + vw * t.w;
        p += __shfl_xor_sync(0xffffffffu, p, 1);
        p += __shfl_xor_sync(0xffffffffu, p, 2);
        p += __shfl_xor_sync(0xffffffffu, p, 4);
        p += __shfl_xor_sync(0xffffffffu, p, 8);
        float w = expf(p);
        if ((lane & 15) == 0)
            atomicAdd(&zsum[(long)d * HEADS + head], w);
        a.x *= w; a.y *= w; a.z *= w; a.w *= w;
        red_add_v4(accd + idx * 4, a);
    }
}

// ---------------- fused edge pass, layer 2 ----------------------------------
__global__ __launch_bounds__(256)
void edge_fused_c256(const float* __restrict__ xl, const float* __restrict__ xr,
                     const int* __restrict__ src, const int* __restrict__ dst,
                     const float* __restrict__ att,
                     float* __restrict__ acc, float* __restrict__ zsum)
{
    int e = blockIdx.x * 8 + (threadIdx.x >> 5);
    int lane = threadIdx.x & 31;
    int s = src[e], d = dst[e];
    const float4* pl = (const float4*)(xl + (long)s * 1536);
    const float4* pr = (const float4*)(xr + (long)d * 1536);
    float4 a0 = pl[lane],     a1 = pl[32 + lane];
    float4 b0 = pr[lane],     b1 = pr[32 + lane];
    float4 t0 = __ldg((const float4*)(att + lane * 4));
    float4 t1 = __ldg((const float4*)(att + 128 + lane * 4));
    float p;
    {
        float vx = a0.x + b0.x; vx = vx > 0.f ? vx : 0.2f * vx;
        float vy = a0.y + b0.y; vy = vy > 0.f ? vy : 0.2f * vy;
        float vz = a0.z + b0.z; vz = vz > 0.f ? vz : 0.2f * vz;
        float vw = a0.w + b0.w; vw = vw > 0.f ? vw : 0.2f * vw;
        p = vx * t0.x + vy * t0.y + vz * t0.z + vw * t0.w;
        vx = a1.x + b1.x; vx = vx > 0.f ? vx : 0.2f * vx;
        vy = a1.y + b1.y; vy = vy > 0.f ? vy : 0.2f * vy;
        vz = a1.z + b1.z; vz = vz > 0.f ? vz : 0.2f * vz;
        vw = a1.w + b1.w; vw = vw > 0.f ? vw : 0.2f * vw;
        p += vx * t1.x + vy * t1.y + vz * t1.z + vw * t1.w;
    }
    p = warp_sum(p);
    float w = expf(p);
    if (lane == 0) atomicAdd(&zsum[d], w);
    float* accd = acc + (long)d * DOUT;
    a0.x *= w; a0.y *= w; a0.z *= w; a0.w *= w;
    a1.x *= w; a1.y *= w; a1.z *= w; a1.w *= w;
    red_add_v4(accd + lane * 4, a0);
    red_add_v4(accd + 128 + lane * 4, a1);
}

// ---------------- fused: normalize + bias + elu + residual + layernorm ------
__global__ __launch_bounds__(128)
void fuse_l01(const float* __restrict__ acc3, const float* __restrict__ z3,
              const float* __restrict__ b0, const float* __restrict__ b1,
              const float* __restrict__ b2,
              const float* __restrict__ res,
              const float* __restrict__ gamma, const float* __restrict__ beta,
              float* __restrict__ out, __half* __restrict__ out16)
{
    int i = blockIdx.x;
    int t = threadIdx.x;
    float v[4];
    float s = 0.f, s2 = 0.f;
    #pragma unroll
    for (int j = 0; j < 4; j++) {
        int c = j * 128 + t;
        int head = c >> 6;
        float x = b0[c] + b1[c] + b2[c];
        #pragma unroll
        for (int et = 0; et < 3; et++) {
            float z = z3[(long)et * NN * HEADS + (long)i * HEADS + head];
            float rz = z != 0.f ? 1.f / z : 0.f;
            x += acc3[(long)et * NN * DH + (long)i * DH + c] * rz;
        }
        x = x > 0.f ? x : expm1f(x);
        x += res[(long)i * DH + c];
        v[j] = x; s += x; s2 += x * x;
    }
    s = warp_sum(s); s2 = warp_sum(s2);
    __shared__ float sh1[4], sh2[4];
    int w = t >> 5, l = t & 31;
    if (l == 0) { sh1[w] = s; sh2[w] = s2; }
    __syncthreads();
    s = sh1[0] + sh1[1] + sh1[2] + sh1[3];
    s2 = sh2[0] + sh2[1] + sh2[2] + sh2[3];
    float mu = s * (1.f / DH);
    float var = s2 * (1.f / DH) - mu * mu;
    float inv = rsqrtf(var + 1e-5f);
    #pragma unroll
    for (int j = 0; j < 4; j++) {
        int c = j * 128 + t;
        float o = (v[j] - mu) * inv * gamma[c] + beta[c];
        out[(long)i * DH + c] = o;
        out16[(long)i * DH + c] = __float2half_rn(o);
    }
}

__global__ __launch_bounds__(128)
void fuse_l2(const float* __restrict__ acc3, const float* __restrict__ z3,
             const float* __restrict__ b0, const float* __restrict__ b1,
             const float* __restrict__ b2,
             const float* __restrict__ gamma, const float* __restrict__ beta,
             float* __restrict__ out)
{
    int i = blockIdx.x;
    int t = threadIdx.x;
    float rz[3];
    #pragma unroll
    for (int et = 0; et < 3; et++) {
        float z = z3[(long)et * NN + i];
        rz[et] = z != 0.f ? 1.f / z : 0.f;
    }
    float v[2];
    float s = 0.f, s2 = 0.f;
    #pragma unroll
    for (int j = 0; j < 2; j++) {
        int c = j * 128 + t;
        float x = b0[c] + b1[c] + b2[c];
        #pragma unroll
        for (int et = 0; et < 3; et++)
            x += acc3[(long)et * NN * DOUT + (long)i * DOUT + c] * rz[et];
        x = x > 0.f ? x : expm1f(x);
        v[j] = x; s += x; s2 += x * x;
    }
    s = warp_sum(s); s2 = warp_sum(s2);
    __shared__ float sh1[4], sh2[4];
    int w = t >> 5, l = t & 31;
    if (l == 0) { sh1[w] = s; sh2[w] = s2; }
    __syncthreads();
    s = sh1[0] + sh1[1] + sh1[2] + sh1[3];
    s2 = sh2[0] + sh2[1] + sh2[2] + sh2[3];
    float mu = s * (1.f / DOUT);
    float var = s2 * (1.f / DOUT) - mu * mu;
    float inv = rsqrtf(var + 1e-5f);
    #pragma unroll
    for (int j = 0; j < 2; j++) {
        int c = j * 128 + t;
        out[(long)i * DOUT + c] = (v[j] - mu) * inv * gamma[c] + beta[c];
    }
}

// ---------------- host ------------------------------------------------------
static inline void run_gemm(const __half* A, const __half* B, const float* bias,
                            float* C, __half* C16, int M, int N, int act)
{
    dim3 grid(N / GBN, (M + GBM - 1) / GBM);
    hgemm_bias_act<<<grid, 256, GEMM_SMEM>>>(A, B, bias, C, C16, M, N, act);
}

static inline void convert(const float* in, __half* out, long n)
{
    long n4 = n / 4;
    f32_to_f16<<<(unsigned)((n4 + 255) / 256), 256>>>(in, out, (int)n4);
}

extern "C" void kernel_launch(void* const* d_in, const int* in_sizes, int n_in,
                              void* d_out, int out_size)
{
    const float* x          = (const float*)d_in[0];
    const int*   edge_index = (const int*)  d_in[1];
    const float* proj_w     = (const float*)d_in[2];
    const float* proj_b     = (const float*)d_in[3];
    const float* l01_ll_w   = (const float*)d_in[4];
    const float* l01_ll_b   = (const float*)d_in[5];
    const float* l01_lr_w   = (const float*)d_in[6];
    const float* l01_lr_b   = (const float*)d_in[7];
    const float* l01_att    = (const float*)d_in[8];
    const float* l01_bias   = (const float*)d_in[9];
    const float* l2_ll_w    = (const float*)d_in[10];
    const float* l2_ll_b    = (const float*)d_in[11];
    const float* l2_lr_w    = (const float*)d_in[12];
    const float* l2_lr_b    = (const float*)d_in[13];
    const float* l2_att     = (const float*)d_in[14];
    const float* l2_bias    = (const float*)d_in[15];
    const float* ln01_gamma = (const float*)d_in[16];
    const float* ln01_beta  = (const float*)d_in[17];
    const float* ln2_gamma  = (const float*)d_in[18];
    const float* ln2_beta   = (const float*)d_in[19];

    float *h, *h2, *xcat, *acc3, *zsum, *bcat01, *bcat2;
    __half *a16, *x16, *w_proj, *wcat01, *wcat2;
    cudaGetSymbolAddress((void**)&h,      g_h);
    cudaGetSymbolAddress((void**)&h2,     g_h2);
    cudaGetSymbolAddress((void**)&xcat,   g_xcat);
    cudaGetSymbolAddress((void**)&acc3,   g_acc3);
    cudaGetSymbolAddress((void**)&zsum,   g_zsum);
    cudaGetSymbolAddress((void**)&a16,    g_a16);
    cudaGetSymbolAddress((void**)&x16,    g_x16);
    cudaGetSymbolAddress((void**)&w_proj, g_w16_proj);
    cudaGetSymbolAddress((void**)&wcat01, g_wcat01);
    cudaGetSymbolAddress((void**)&wcat2,  g_wcat2);
    cudaGetSymbolAddress((void**)&bcat01, g_bcat01);
    cudaGetSymbolAddress((void**)&bcat2,  g_bcat2);

    cudaFuncSetAttribute(hgemm_bias_act,
                         cudaFuncAttributeMaxDynamicSharedMemorySize, GEMM_SMEM);

    // one-time conversions / packs
    convert(x, x16, (long)NN * DH);
    convert(proj_w, w_proj, (long)DH * DH);
    pack_w01<<<(2 * 3 * DH * DH / 4 + 255) / 256, 256>>>(l01_ll_w, l01_lr_w, wcat01);
    pack_w2 <<<(3 * DH * DOUT / 4 + 255) / 256, 256>>>(l2_ll_w, l2_lr_w, wcat2);
    pack_b01<<<(2 * 3 * DH + 255) / 256, 256>>>(l01_ll_b, l01_lr_b, bcat01);
    pack_b2 <<<(3 * DOUT + 255) / 256, 256>>>(l2_ll_b, l2_lr_b, bcat2);

    // input projection + ELU (fp32 out h, fp16 out a16)
    run_gemm(x16, w_proj, proj_b, h, a16, NN, 512, 1);

    float* cur = h;
    float* nxt = h2;

    for (int li = 0; li < 2; li++) {
        cudaMemsetAsync(acc3, 0, (size_t)3 * NN * DH * sizeof(float));
        cudaMemsetAsync(zsum, 0, (size_t)3 * NN * HEADS * sizeof(float));
        run_gemm(a16, wcat01 + (size_t)li * DH * 3072, bcat01 + (size_t)li * 3072,
                 xcat, nullptr, NN, 3072, 0);
        for (int et = 0; et < 3; et++) {
            const int* src = edge_index + (size_t)et * 2 * EE;
            const int* dst = src + EE;
            edge_fused_h8<<<EE / 8, 256>>>(
                xcat + (size_t)et * 512, xcat + 1536 + (size_t)et * 512,
                src, dst,
                l01_att + (size_t)(li * 3 + et) * HEADS * HID,
                acc3 + (size_t)et * NN * DH,
                zsum + (size_t)et * NN * HEADS);
        }
        fuse_l01<<<NN, 128>>>(acc3, zsum,
                              l01_bias + (size_t)(li * 3 + 0) * DH,
                              l01_bias + (size_t)(li * 3 + 1) * DH,
                              l01_bias + (size_t)(li * 3 + 2) * DH,
                              cur,
                              ln01_gamma + (size_t)li * DH,
                              ln01_beta  + (size_t)li * DH,
                              nxt, a16);
        float* tmp = cur; cur = nxt; nxt = tmp;
    }

    // layer 2 (heads=1, out=256)
    cudaMemsetAsync(acc3, 0, (size_t)3 * NN * DOUT * sizeof(float));
    cudaMemsetAsync(zsum, 0, (size_t)3 * NN * sizeof(float));
    run_gemm(a16, wcat2, bcat2, xcat, nullptr, NN, 1536, 0);
    for (int et = 0; et < 3; et++) {
        const int* src = edge_index + (size_t)et * 2 * EE;
        const int* dst = src + EE;
        edge_fused_c256<<<EE / 8, 256>>>(
            xcat + (size_t)et * 256, xcat + 768 + (size_t)et * 256,
            src, dst,
            l2_att + (size_t)et * DOUT,
            acc3 + (size_t)et * NN * DOUT,
            zsum + (size_t)et * NN);
    }
    fuse_l2<<<NN, 128>>>(acc3, zsum,
                         l2_bias + 0 * DOUT, l2_bias + 1 * DOUT, l2_bias + 2 * DOUT,
                         ln2_gamma, ln2_beta, (float*)d_out);
}